// round 5
// baseline (speedup 1.0000x reference)
#include <cuda_runtime.h>
#include <math.h>

#define STEPS 9

// ---------------- packed pair weights (device globals; no allocation) ----
// layout: [(cpair*9 + k) * O + o] as float2
__device__ float2 g_p_conv0[128 * 9 * 128];  // C=256 -> 128 cp, O=128
__device__ float2 g_p_conv1[ 64 * 9 * 128];  // C=128 -> 64 cp,  O=128
// cx0 cp order: cp0..63 = x channel pairs; cp64 = (ch130 v_first, 0); cp65 = (v_p2, v_p1)
__device__ float2 g_p_cx0 [ 66 * 9 * 256];
__device__ float2 g_p_ch0 [ 32 * 9 * 256];
__device__ float2 g_p_cx1 [ 32 * 9 * 256];
__device__ float2 g_p_ch1 [ 32 * 9 * 256];

__global__ void pack_weights(const float* __restrict__ w0, const float* __restrict__ w1,
                             const float* __restrict__ wcx0, const float* __restrict__ wch0,
                             const float* __restrict__ wcx1, const float* __restrict__ wch1)
{
    int i = blockIdx.x * blockDim.x + threadIdx.x;
    const int s0 = 128 * 9 * 128, s1 = 64 * 9 * 128, s2 = 66 * 9 * 256, s3 = 32 * 9 * 256;
    if (i < s0) {
        int o = i % 128, ck = i / 128, cp = ck / 9, k = ck % 9;
        g_p_conv0[i] = make_float2(w0[(o * 256 + 2 * cp) * 9 + k],
                                   w0[(o * 256 + 2 * cp + 1) * 9 + k]);
        return;
    }
    i -= s0;
    if (i < s1) {
        int o = i % 128, ck = i / 128, cp = ck / 9, k = ck % 9;
        g_p_conv1[i] = make_float2(w1[(o * 128 + 2 * cp) * 9 + k],
                                   w1[(o * 128 + 2 * cp + 1) * 9 + k]);
        return;
    }
    i -= s1;
    if (i < s2) {
        int o = i % 256, ck = i / 256, cp = ck / 9, k = ck % 9;
        float a, b;
        if (cp < 64)      { a = wcx0[(o * 131 + 2 * cp) * 9 + k];
                            b = wcx0[(o * 131 + 2 * cp + 1) * 9 + k]; }
        else if (cp == 64){ a = wcx0[(o * 131 + 130) * 9 + k]; b = 0.0f; }
        else              { a = wcx0[(o * 131 + 128) * 9 + k];
                            b = wcx0[(o * 131 + 129) * 9 + k]; }
        g_p_cx0[i] = make_float2(a, b);
        return;
    }
    i -= s2;
    if (i < s3) {
        int o = i % 256, ck = i / 256, cp = ck / 9, k = ck % 9;
        g_p_ch0[i] = make_float2(wch0[(o * 64 + 2 * cp) * 9 + k],
                                 wch0[(o * 64 + 2 * cp + 1) * 9 + k]);
        return;
    }
    i -= s3;
    if (i < s3) {
        int o = i % 256, ck = i / 256, cp = ck / 9, k = ck % 9;
        g_p_cx1[i] = make_float2(wcx1[(o * 64 + 2 * cp) * 9 + k],
                                 wcx1[(o * 64 + 2 * cp + 1) * 9 + k]);
        return;
    }
    i -= s3;
    if (i < s3) {
        int o = i % 256, ck = i / 256, cp = ck / 9, k = ck % 9;
        g_p_ch1[i] = make_float2(wch1[(o * 64 + 2 * cp) * 9 + k],
                                 wch1[(o * 64 + 2 * cp + 1) * 9 + k]);
        return;
    }
}

// ---------------- packed fp32x2 helpers ----------------
__device__ __forceinline__ void ffma2(unsigned long long& d, unsigned long long a,
                                      unsigned long long b)
{
    asm("fma.rn.f32x2 %0, %1, %2, %0;" : "+l"(d) : "l"(a), "l"(b));
}
__device__ __forceinline__ unsigned long long pack2(float lo, float hi)
{
    unsigned long long r;
    asm("mov.b64 %0, {%1, %2};" : "=l"(r) : "f"(lo), "f"(hi));
    return r;
}
__device__ __forceinline__ float fold2(unsigned long long v)
{
    float lo, hi;
    asm("mov.b64 {%0, %1}, %2;" : "=f"(lo), "=f"(hi) : "l"(v));
    return lo + hi;
}
__device__ __forceinline__ int ppad(int p) { return p + 2 * (p / 7) + 10; }
__device__ __forceinline__ float sigm(float v) { return 1.0f / (1.0f + expf(-v)); }

// 3x3 SAME conv over channel-pair-interleaved padded planes (u64 = float pair).
// plane: [cp][padded 9x9][2 floats]. Thread owns out-channel o and the output
// tile rows [R0, R0+NR) x cols [C0, C0+NC). Window held as [3][NC+2] ring (cols
// C0..C0+NC+1 of three padded rows). acc layout: acc[r*NC + x].
template <int NR, int R0, int NC, int C0>
__device__ __forceinline__ void conv_tile(const float2* __restrict__ W, const int CP,
                                          const int Ostride, const float* __restrict__ plane,
                                          const int o, unsigned long long* acc)
{
    const unsigned long long* Pl = (const unsigned long long*)plane;
    const unsigned long long* Wp = (const unsigned long long*)W + o;
    const int NW = NC + 2;

    for (int cp = 0; cp < CP; ++cp) {
        unsigned long long wA[9];
#pragma unroll
        for (int k = 0; k < 9; ++k) wA[k] = __ldg(Wp + ((size_t)cp * 9 + k) * Ostride);

        const unsigned long long* pb = Pl + cp * 81;
        unsigned long long win[3][NW];
#pragma unroll
        for (int j = 0; j < NW; ++j) win[R0 % 3][j] = pb[R0 * 9 + C0 + j];
#pragma unroll
        for (int j = 0; j < NW; ++j) win[(R0 + 1) % 3][j] = pb[(R0 + 1) * 9 + C0 + j];

#pragma unroll
        for (int r = 0; r < NR; ++r) {
            const int rl = R0 + r + 2;
#pragma unroll
            for (int j = 0; j < NW; ++j) win[rl % 3][j] = pb[rl * 9 + C0 + j];
#pragma unroll
            for (int ky = 0; ky < 3; ++ky) {
                const int rr = (R0 + r + ky) % 3;
#pragma unroll
                for (int kx = 0; kx < 3; ++kx) {
                    const unsigned long long wv = wA[ky * 3 + kx];
#pragma unroll
                    for (int x = 0; x < NC; ++x)
                        ffma2(acc[r * NC + x], wv, win[rr][x + kx]);
                }
            }
        }
    }
}

// ---------------- SMEM layout (floats) ----------------
//   h0P  @ 0     : 5184    h1P @ 5184 : 5184
//   c0   @ 10368 : 3136    c1  @ 13504: 3136
//   gsm  @ 16640 : 12544   gxc @ 29184: 12544
//   vtxP @ 41728 : 162     lg  @ 41890: 50 ; pred @ 41940
// phase A overlays: xin @ 0 (20736), xoutP @ 29184 (10368), x2P @ 0 (10530)
#define SM_H0   0
#define SM_H1   5184
#define SM_C0   10368
#define SM_C1   13504
#define SM_G    16640
#define SM_GXC  29184
#define SM_VTX  41728
#define SM_LG   41890
#define SM_PRED 41940
#define SMEM_FLOATS 41952

#define NT 512

__global__ __launch_bounds__(NT, 1)
void polyrnn_main(const float* __restrict__ x, const int* __restrict__ first_vertex,
                  const float* __restrict__ b0, const float* __restrict__ b1,
                  const float* __restrict__ bcx0, const float* __restrict__ bch0,
                  const float* __restrict__ bcx1, const float* __restrict__ bch1,
                  const float* __restrict__ fcw, const float* __restrict__ fcb,
                  float* __restrict__ out)
{
    extern __shared__ float sm[];
    float* h0P   = sm + SM_H0;
    float* h1P   = sm + SM_H1;
    float* c0s   = sm + SM_C0;
    float* c1s   = sm + SM_C1;
    float* gsm   = sm + SM_G;
    float* gxc   = sm + SM_GXC;
    float* vtxP  = sm + SM_VTX;
    float* lg    = sm + SM_LG;
    int*   predp = (int*)(sm + SM_PRED);
    float* xin   = sm;            // phase A
    float* xoutP = sm + SM_GXC;   // phase A
    float* x2P   = sm;            // phase A

    const int s   = blockIdx.x;
    const int tid = threadIdx.x;

    // ---- 1: zero xin + xoutP regions ----
    for (int i = tid; i < SM_GXC + 10368; i += NT) sm[i] = 0.0f;
    __syncthreads();

    // ---- 2: load x into pair-interleaved padded planes ----
    const float* xs = x + (size_t)s * (256 * 49);
    for (int i = tid; i < 256 * 49; i += NT) {
        int c = i / 49, p = i % 49;
        xin[(c >> 1) * 162 + ppad(p) * 2 + (c & 1)] = xs[i];
    }
    __syncthreads();

    // ---- 3: conv0 (256->128) + ReLU -> xoutP ; quadrant mapping ----
    {
        const int o = tid & 127, g = tid >> 7;   // g: (row-half, col-half)
        const unsigned long long binit = pack2(b0[o], 0.0f);
        unsigned long long a[16];
#pragma unroll
        for (int i = 0; i < 16; ++i) a[i] = binit;
        if (g == 0) {
            conv_tile<4, 0, 4, 0>(g_p_conv0, 128, 128, xin, o, a);
#pragma unroll
            for (int r = 0; r < 4; ++r)
#pragma unroll
                for (int xq = 0; xq < 4; ++xq)
                    xoutP[(o >> 1) * 162 + ((r + 1) * 9 + xq + 1) * 2 + (o & 1)] =
                        fmaxf(fold2(a[r * 4 + xq]), 0.0f);
        } else if (g == 1) {
            conv_tile<4, 0, 3, 4>(g_p_conv0, 128, 128, xin, o, a);
#pragma unroll
            for (int r = 0; r < 4; ++r)
#pragma unroll
                for (int xq = 0; xq < 3; ++xq)
                    xoutP[(o >> 1) * 162 + ((r + 1) * 9 + xq + 5) * 2 + (o & 1)] =
                        fmaxf(fold2(a[r * 3 + xq]), 0.0f);
        } else if (g == 2) {
            conv_tile<3, 4, 4, 0>(g_p_conv0, 128, 128, xin, o, a);
#pragma unroll
            for (int r = 0; r < 3; ++r)
#pragma unroll
                for (int xq = 0; xq < 4; ++xq)
                    xoutP[(o >> 1) * 162 + ((r + 5) * 9 + xq + 1) * 2 + (o & 1)] =
                        fmaxf(fold2(a[r * 4 + xq]), 0.0f);
        } else {
            conv_tile<3, 4, 3, 4>(g_p_conv0, 128, 128, xin, o, a);
#pragma unroll
            for (int r = 0; r < 3; ++r)
#pragma unroll
                for (int xq = 0; xq < 3; ++xq)
                    xoutP[(o >> 1) * 162 + ((r + 5) * 9 + xq + 5) * 2 + (o & 1)] =
                        fmaxf(fold2(a[r * 3 + xq]), 0.0f);
        }
    }
    __syncthreads();

    // ---- 4: conv1 (128->128) + ReLU -> x2P cps 0..63 ----
    {
        const int o = tid & 127, g = tid >> 7;
        const unsigned long long binit = pack2(b1[o], 0.0f);
        unsigned long long a[16];
#pragma unroll
        for (int i = 0; i < 16; ++i) a[i] = binit;
        if (g == 0) {
            conv_tile<4, 0, 4, 0>(g_p_conv1, 64, 128, xoutP, o, a);
#pragma unroll
            for (int r = 0; r < 4; ++r)
#pragma unroll
                for (int xq = 0; xq < 4; ++xq)
                    x2P[(o >> 1) * 162 + ((r + 1) * 9 + xq + 1) * 2 + (o & 1)] =
                        fmaxf(fold2(a[r * 4 + xq]), 0.0f);
        } else if (g == 1) {
            conv_tile<4, 0, 3, 4>(g_p_conv1, 64, 128, xoutP, o, a);
#pragma unroll
            for (int r = 0; r < 4; ++r)
#pragma unroll
                for (int xq = 0; xq < 3; ++xq)
                    x2P[(o >> 1) * 162 + ((r + 1) * 9 + xq + 5) * 2 + (o & 1)] =
                        fmaxf(fold2(a[r * 3 + xq]), 0.0f);
        } else if (g == 2) {
            conv_tile<3, 4, 4, 0>(g_p_conv1, 64, 128, xoutP, o, a);
#pragma unroll
            for (int r = 0; r < 3; ++r)
#pragma unroll
                for (int xq = 0; xq < 4; ++xq)
                    x2P[(o >> 1) * 162 + ((r + 5) * 9 + xq + 1) * 2 + (o & 1)] =
                        fmaxf(fold2(a[r * 4 + xq]), 0.0f);
        } else {
            conv_tile<3, 4, 3, 4>(g_p_conv1, 64, 128, xoutP, o, a);
#pragma unroll
            for (int r = 0; r < 3; ++r)
#pragma unroll
                for (int xq = 0; xq < 3; ++xq)
                    x2P[(o >> 1) * 162 + ((r + 5) * 9 + xq + 5) * 2 + (o & 1)] =
                        fmaxf(fold2(a[r * 3 + xq]), 0.0f);
        }
    }
    __syncthreads();

    // ---- 5: v_first plane at x2P cp64 ----
    if (tid < 162) x2P[64 * 162 + tid] = 0.0f;
    __syncthreads();
    if (tid == 0) {
        int v = first_vertex[s];
        x2P[64 * 162 + ppad(v) * 2 + 0] = 1.0f;
    }
    __syncthreads();

    // ---- 6: gxc = bias_g0 + conv(x2P cps0..64; cx0) ; col-half mapping ----
    {
        const int o = tid & 255, g = tid >> 8;
        const float bg0 = bcx0[o] + bch0[o];
        const unsigned long long binit = pack2(bg0, 0.0f);
        unsigned long long a[28];
#pragma unroll
        for (int i = 0; i < 28; ++i) a[i] = binit;
        if (g == 0) {
            conv_tile<7, 0, 4, 0>(g_p_cx0, 65, 256, x2P, o, a);
#pragma unroll
            for (int r = 0; r < 7; ++r)
#pragma unroll
                for (int xq = 0; xq < 4; ++xq)
                    gxc[o * 49 + r * 7 + xq] = fold2(a[r * 4 + xq]);
        } else {
            conv_tile<7, 0, 3, 4>(g_p_cx0, 65, 256, x2P, o, a);
#pragma unroll
            for (int r = 0; r < 7; ++r)
#pragma unroll
                for (int xq = 0; xq < 3; ++xq)
                    gxc[o * 49 + r * 7 + 4 + xq] = fold2(a[r * 3 + xq]);
        }
    }
    __syncthreads();

    // ---- 7: zero h0,h1,c0,c1 + vtxP; init v_p1 = v_first one-hot ----
    for (int i = tid; i < SM_G; i += NT) sm[i] = 0.0f;
    if (tid < 162) vtxP[tid] = 0.0f;
    __syncthreads();
    if (tid == 0) {
        int v = first_vertex[s];
        vtxP[ppad(v) * 2 + 1] = 1.0f;
    }
    __syncthreads();

    const int o_g  = tid & 255;
    const int ghalf = tid >> 8;
    const float bias_g1 = bcx1[o_g] + bch1[o_g];
    const float2* cx0_dyn = g_p_cx0 + 65 * 9 * 256;
    const int warp = tid >> 5, lane = tid & 31;

    for (int t = 0; t < STEPS; ++t) {
        // ---- layer0 gates: gxc + conv(vtxP; cx0_dyn) + conv(h0P; ch0) ----
        {
            unsigned long long a[28];
            if (ghalf == 0) {
#pragma unroll
                for (int r = 0; r < 7; ++r)
#pragma unroll
                    for (int xq = 0; xq < 4; ++xq)
                        a[r * 4 + xq] = pack2(gxc[o_g * 49 + r * 7 + xq], 0.0f);
                conv_tile<7, 0, 4, 0>(cx0_dyn, 1, 256, vtxP, o_g, a);
                conv_tile<7, 0, 4, 0>(g_p_ch0, 32, 256, h0P, o_g, a);
#pragma unroll
                for (int r = 0; r < 7; ++r)
#pragma unroll
                    for (int xq = 0; xq < 4; ++xq)
                        gsm[o_g * 49 + r * 7 + xq] = fold2(a[r * 4 + xq]);
            } else {
#pragma unroll
                for (int r = 0; r < 7; ++r)
#pragma unroll
                    for (int xq = 0; xq < 3; ++xq)
                        a[r * 3 + xq] = pack2(gxc[o_g * 49 + r * 7 + 4 + xq], 0.0f);
                conv_tile<7, 0, 3, 4>(cx0_dyn, 1, 256, vtxP, o_g, a);
                conv_tile<7, 0, 3, 4>(g_p_ch0, 32, 256, h0P, o_g, a);
#pragma unroll
                for (int r = 0; r < 7; ++r)
#pragma unroll
                    for (int xq = 0; xq < 3; ++xq)
                        gsm[o_g * 49 + r * 7 + 4 + xq] = fold2(a[r * 3 + xq]);
            }
        }
        __syncthreads();

        // ---- LSTM0 ----
        for (int i = tid; i < 3136; i += NT) {
            int c = i / 49, p = i - c * 49;
            float ig = sigm(gsm[c * 49 + p]);
            float fg = sigm(gsm[(c + 64) * 49 + p]);
            float gg = tanhf(gsm[(c + 128) * 49 + p]);
            float og = sigm(gsm[(c + 192) * 49 + p]);
            float cy = fg * c0s[i] + ig * gg;
            c0s[i] = cy;
            h0P[(c >> 1) * 162 + ppad(p) * 2 + (c & 1)] = og * tanhf(cy);
        }
        __syncthreads();

        // ---- layer1 gates: conv(h0P; cx1) + conv(h1P; ch1) ----
        {
            unsigned long long a[28];
            const unsigned long long binit = pack2(bias_g1, 0.0f);
#pragma unroll
            for (int i = 0; i < 28; ++i) a[i] = binit;
            if (ghalf == 0) {
                conv_tile<7, 0, 4, 0>(g_p_cx1, 32, 256, h0P, o_g, a);
                conv_tile<7, 0, 4, 0>(g_p_ch1, 32, 256, h1P, o_g, a);
#pragma unroll
                for (int r = 0; r < 7; ++r)
#pragma unroll
                    for (int xq = 0; xq < 4; ++xq)
                        gsm[o_g * 49 + r * 7 + xq] = fold2(a[r * 4 + xq]);
            } else {
                conv_tile<7, 0, 3, 4>(g_p_cx1, 32, 256, h0P, o_g, a);
                conv_tile<7, 0, 3, 4>(g_p_ch1, 32, 256, h1P, o_g, a);
#pragma unroll
                for (int r = 0; r < 7; ++r)
#pragma unroll
                    for (int xq = 0; xq < 3; ++xq)
                        gsm[o_g * 49 + r * 7 + 4 + xq] = fold2(a[r * 3 + xq]);
            }
        }
        __syncthreads();

        // ---- LSTM1 ----
        for (int i = tid; i < 3136; i += NT) {
            int c = i / 49, p = i - c * 49;
            float ig = sigm(gsm[c * 49 + p]);
            float fg = sigm(gsm[(c + 64) * 49 + p]);
            float gg = tanhf(gsm[(c + 128) * 49 + p]);
            float og = sigm(gsm[(c + 192) * 49 + p]);
            float cy = fg * c1s[i] + ig * gg;
            c1s[i] = cy;
            h1P[(c >> 1) * 162 + ppad(p) * 2 + (c & 1)] = og * tanhf(cy);
        }
        __syncthreads();

        // ---- fc: logits[50] over 16 warps ----
        for (int o = warp; o < 50; o += 16) {
            float ssum = 0.0f;
            const float* wr = fcw + o * 3136;
            int c = 0, p = lane;
            for (int j = lane; j < 3136; j += 32) {
                ssum += wr[j] * h1P[(c >> 1) * 162 + ppad(p) * 2 + (c & 1)];
                p += 32;
                if (p >= 49) { p -= 49; ++c; }
            }
#pragma unroll
            for (int d = 16; d; d >>= 1) ssum += __shfl_down_sync(0xffffffffu, ssum, d);
            if (lane == 0) lg[o] = ssum + fcb[o];
        }
        __syncthreads();

        // ---- emit + argmax (first max wins) ----
        if (tid < 50) out[((size_t)s * STEPS + t) * 50 + tid] = lg[tid];
        if (tid == 0) {
            int best = 0;
            float bv = lg[0];
#pragma unroll 1
            for (int o2 = 1; o2 < 50; ++o2) {
                float v = lg[o2];
                if (v > bv) { bv = v; best = o2; }
            }
            *predp = best;
        }
        __syncthreads();

        // ---- feedback: (v_p2, v_p1) <- (v_p1, one_hot(pred)); class 49 -> zeros ----
        {
            int pr = *predp;
            if (tid < 49) {
                int a2 = ppad(tid) * 2;
                vtxP[a2 + 0] = vtxP[a2 + 1];
                vtxP[a2 + 1] = (pr == tid) ? 1.0f : 0.0f;
            }
        }
        __syncthreads();
    }
}

extern "C" void kernel_launch(void* const* d_in, const int* in_sizes, int n_in,
                              void* d_out, int out_size)
{
    const float* x    = (const float*)d_in[0];
    const int*   fv   = (const int*)  d_in[1];
    const float* w0   = (const float*)d_in[2];
    const float* b0   = (const float*)d_in[3];
    const float* w1   = (const float*)d_in[4];
    const float* b1   = (const float*)d_in[5];
    const float* wcx0 = (const float*)d_in[6];
    const float* bcx0 = (const float*)d_in[7];
    const float* wch0 = (const float*)d_in[8];
    const float* bch0 = (const float*)d_in[9];
    const float* wcx1 = (const float*)d_in[10];
    const float* bcx1 = (const float*)d_in[11];
    const float* wch1 = (const float*)d_in[12];
    const float* bch1 = (const float*)d_in[13];
    const float* fcw  = (const float*)d_in[14];
    const float* fcb  = (const float*)d_in[15];
    float* out = (float*)d_out;

    const int n = in_sizes[1];  // batch

    const int total = 128 * 9 * 128 + 64 * 9 * 128 + 66 * 9 * 256 + 3 * 32 * 9 * 256;
    pack_weights<<<(total + 255) / 256, 256>>>(w0, w1, wcx0, wch0, wcx1, wch1);

    const int smem_bytes = SMEM_FLOATS * 4;
    cudaFuncSetAttribute(polyrnn_main, cudaFuncAttributeMaxDynamicSharedMemorySize, smem_bytes);
    polyrnn_main<<<n, NT, smem_bytes>>>(x, fv, b0, b1, bcx0, bch0, bcx1, bch1, fcw, fcb, out);
}

// round 7
// speedup vs baseline: 1.6006x; 1.6006x over previous
#include <cuda_runtime.h>
#include <math.h>

#define STEPS 9

// ---------------- packed pair weights (device globals; no allocation) ----
// layout: [(cpair*9 + k) * O + o] as float2
__device__ float2 g_p_conv0[128 * 9 * 128];  // C=256 -> 128 cp, O=128
__device__ float2 g_p_conv1[ 64 * 9 * 128];  // C=128 -> 64 cp,  O=128
// cx0 cp order: cp0..63 = x channel pairs; cp64 = (ch130 v_first, 0); cp65 = (v_p2, v_p1)
__device__ float2 g_p_cx0 [ 66 * 9 * 256];
__device__ float2 g_p_ch0 [ 32 * 9 * 256];
__device__ float2 g_p_cx1 [ 32 * 9 * 256];
__device__ float2 g_p_ch1 [ 32 * 9 * 256];

__global__ void pack_weights(const float* __restrict__ w0, const float* __restrict__ w1,
                             const float* __restrict__ wcx0, const float* __restrict__ wch0,
                             const float* __restrict__ wcx1, const float* __restrict__ wch1)
{
    int i = blockIdx.x * blockDim.x + threadIdx.x;
    const int s0 = 128 * 9 * 128, s1 = 64 * 9 * 128, s2 = 66 * 9 * 256, s3 = 32 * 9 * 256;
    if (i < s0) {
        int o = i % 128, ck = i / 128, cp = ck / 9, k = ck % 9;
        g_p_conv0[i] = make_float2(w0[(o * 256 + 2 * cp) * 9 + k],
                                   w0[(o * 256 + 2 * cp + 1) * 9 + k]);
        return;
    }
    i -= s0;
    if (i < s1) {
        int o = i % 128, ck = i / 128, cp = ck / 9, k = ck % 9;
        g_p_conv1[i] = make_float2(w1[(o * 128 + 2 * cp) * 9 + k],
                                   w1[(o * 128 + 2 * cp + 1) * 9 + k]);
        return;
    }
    i -= s1;
    if (i < s2) {
        int o = i % 256, ck = i / 256, cp = ck / 9, k = ck % 9;
        float a, b;
        if (cp < 64)      { a = wcx0[(o * 131 + 2 * cp) * 9 + k];
                            b = wcx0[(o * 131 + 2 * cp + 1) * 9 + k]; }
        else if (cp == 64){ a = wcx0[(o * 131 + 130) * 9 + k]; b = 0.0f; }
        else              { a = wcx0[(o * 131 + 128) * 9 + k];
                            b = wcx0[(o * 131 + 129) * 9 + k]; }
        g_p_cx0[i] = make_float2(a, b);
        return;
    }
    i -= s2;
    if (i < s3) {
        int o = i % 256, ck = i / 256, cp = ck / 9, k = ck % 9;
        g_p_ch0[i] = make_float2(wch0[(o * 64 + 2 * cp) * 9 + k],
                                 wch0[(o * 64 + 2 * cp + 1) * 9 + k]);
        return;
    }
    i -= s3;
    if (i < s3) {
        int o = i % 256, ck = i / 256, cp = ck / 9, k = ck % 9;
        g_p_cx1[i] = make_float2(wcx1[(o * 64 + 2 * cp) * 9 + k],
                                 wcx1[(o * 64 + 2 * cp + 1) * 9 + k]);
        return;
    }
    i -= s3;
    if (i < s3) {
        int o = i % 256, ck = i / 256, cp = ck / 9, k = ck % 9;
        g_p_ch1[i] = make_float2(wch1[(o * 64 + 2 * cp) * 9 + k],
                                 wch1[(o * 64 + 2 * cp + 1) * 9 + k]);
        return;
    }
}

// ---------------- packed fp32x2 helpers ----------------
__device__ __forceinline__ void ffma2(unsigned long long& d, unsigned long long a,
                                      unsigned long long b)
{
    asm("fma.rn.f32x2 %0, %1, %2, %0;" : "+l"(d) : "l"(a), "l"(b));
}
__device__ __forceinline__ unsigned long long pack2(float lo, float hi)
{
    unsigned long long r;
    asm("mov.b64 %0, {%1, %2};" : "=l"(r) : "f"(lo), "f"(hi));
    return r;
}
__device__ __forceinline__ float fold2(unsigned long long v)
{
    float lo, hi;
    asm("mov.b64 {%0, %1}, %2;" : "=f"(lo), "=f"(hi) : "l"(v));
    return lo + hi;
}
__device__ __forceinline__ int ppad(int p) { return p + 2 * (p / 7) + 10; }
__device__ __forceinline__ float sigm(float v) { return 1.0f / (1.0f + expf(-v)); }

// 3x3 SAME conv over channel-pair-interleaved padded planes (u64 = float pair).
// plane: [cp][padded 9x9][2 floats]. Thread owns out-channel o, output rows
// [Y0, Y0+NR) x all 7 cols. OS = out-channel stride (compile-time -> weight tap
// loads become LDG [ptr + imm]). Double-buffered weight prefetch across cp.
// Inner loop order ky,kx,x: 7 independent accumulators between acc reuses.
template <int NR, int Y0, int OS>
__device__ __forceinline__ void conv_pair(const float2* __restrict__ W, const int CP,
                                          const float* __restrict__ plane,
                                          const int o, unsigned long long* acc)
{
    const unsigned long long* pb = (const unsigned long long*)plane;
    const unsigned long long* wptr = (const unsigned long long*)W + o;

    unsigned long long wA[9];
#pragma unroll
    for (int k = 0; k < 9; ++k) wA[k] = __ldg(wptr + k * OS);

    for (int cp = 0; cp < CP; ++cp) {
        const unsigned long long* wnext = (cp + 1 < CP) ? wptr + 9 * OS : wptr;
        unsigned long long wB[9];
#pragma unroll
        for (int k = 0; k < 9; ++k) wB[k] = __ldg(wnext + k * OS);

        unsigned long long win[3][9];
#pragma unroll
        for (int j = 0; j < 9; ++j) win[Y0 % 3][j] = pb[Y0 * 9 + j];
#pragma unroll
        for (int j = 0; j < 9; ++j) win[(Y0 + 1) % 3][j] = pb[(Y0 + 1) * 9 + j];

#pragma unroll
        for (int ry = 0; ry < NR; ++ry) {
            const int rl = Y0 + ry + 2;
#pragma unroll
            for (int j = 0; j < 9; ++j) win[rl % 3][j] = pb[rl * 9 + j];
#pragma unroll
            for (int ky = 0; ky < 3; ++ky) {
                const int rr = (Y0 + ry + ky) % 3;
#pragma unroll
                for (int kx = 0; kx < 3; ++kx) {
                    const unsigned long long wv = wA[ky * 3 + kx];
#pragma unroll
                    for (int x = 0; x < 7; ++x)
                        ffma2(acc[ry * 7 + x], wv, win[rr][x + kx]);
                }
            }
        }
#pragma unroll
        for (int k = 0; k < 9; ++k) wA[k] = wB[k];
        wptr = wnext;
        pb += 81;
    }
}

// ---------------- SMEM layout (floats) ----------------
//   h0P  @ 0     : 5184    h1P @ 5184 : 5184
//   c0   @ 10368 : 3136    c1  @ 13504: 3136
//   gsm  @ 16640 : 12544   gxc @ 29184: 12544
//   vtxP @ 41728 : 162     lg  @ 41890: 50 ; pred @ 41940
// phase A overlays: xin @ 0 (20736), xoutP @ 29184 (10368), x2P @ 0 (10530)
#define SM_H0   0
#define SM_H1   5184
#define SM_C0   10368
#define SM_C1   13504
#define SM_G    16640
#define SM_GXC  29184
#define SM_VTX  41728
#define SM_LG   41890
#define SM_PRED 41940
#define SMEM_FLOATS 41952

__global__ __launch_bounds__(256, 1)
void polyrnn_main(const float* __restrict__ x, const int* __restrict__ first_vertex,
                  const float* __restrict__ b0, const float* __restrict__ b1,
                  const float* __restrict__ bcx0, const float* __restrict__ bch0,
                  const float* __restrict__ bcx1, const float* __restrict__ bch1,
                  const float* __restrict__ fcw, const float* __restrict__ fcb,
                  float* __restrict__ out)
{
    extern __shared__ float sm[];
    float* h0P   = sm + SM_H0;
    float* h1P   = sm + SM_H1;
    float* c0s   = sm + SM_C0;
    float* c1s   = sm + SM_C1;
    float* gsm   = sm + SM_G;
    float* gxc   = sm + SM_GXC;
    float* vtxP  = sm + SM_VTX;
    float* lg    = sm + SM_LG;
    int*   predp = (int*)(sm + SM_PRED);
    float* xin   = sm;            // phase A
    float* xoutP = sm + SM_GXC;   // phase A
    float* x2P   = sm;            // phase A

    const int s   = blockIdx.x;
    const int tid = threadIdx.x;

    // ---- 1: zero xin + xoutP regions (borders must be 0) ----
    for (int i = tid; i < SM_GXC + 10368; i += 256) sm[i] = 0.0f;
    __syncthreads();

    // ---- 2: load x into pair-interleaved padded planes ----
    const float* xs = x + (size_t)s * (256 * 49);
    for (int i = tid; i < 256 * 49; i += 256) {
        int c = i / 49, p = i % 49;
        xin[(c >> 1) * 162 + ppad(p) * 2 + (c & 1)] = xs[i];
    }
    __syncthreads();

    // ---- 3: conv0 (256->128) + ReLU -> xoutP ----
    {
        const int o = tid & 127, half = tid >> 7;
        const unsigned long long binit = pack2(b0[o], 0.0f);
        if (half == 0) {
            unsigned long long a[28];
#pragma unroll
            for (int i = 0; i < 28; ++i) a[i] = binit;
            conv_pair<4, 0, 128>(g_p_conv0, 128, xin, o, a);
#pragma unroll
            for (int i = 0; i < 28; ++i)
                xoutP[(o >> 1) * 162 + ppad(i) * 2 + (o & 1)] = fmaxf(fold2(a[i]), 0.0f);
        } else {
            unsigned long long a[21];
#pragma unroll
            for (int i = 0; i < 21; ++i) a[i] = binit;
            conv_pair<3, 4, 128>(g_p_conv0, 128, xin, o, a);
#pragma unroll
            for (int i = 0; i < 21; ++i)
                xoutP[(o >> 1) * 162 + ppad(28 + i) * 2 + (o & 1)] = fmaxf(fold2(a[i]), 0.0f);
        }
    }
    __syncthreads();

    // ---- 4: conv1 (128->128) + ReLU -> x2P cps 0..63 (overlays xin; borders still 0) ----
    {
        const int o = tid & 127, half = tid >> 7;
        const unsigned long long binit = pack2(b1[o], 0.0f);
        if (half == 0) {
            unsigned long long a[28];
#pragma unroll
            for (int i = 0; i < 28; ++i) a[i] = binit;
            conv_pair<4, 0, 128>(g_p_conv1, 64, xoutP, o, a);
#pragma unroll
            for (int i = 0; i < 28; ++i)
                x2P[(o >> 1) * 162 + ppad(i) * 2 + (o & 1)] = fmaxf(fold2(a[i]), 0.0f);
        } else {
            unsigned long long a[21];
#pragma unroll
            for (int i = 0; i < 21; ++i) a[i] = binit;
            conv_pair<3, 4, 128>(g_p_conv1, 64, xoutP, o, a);
#pragma unroll
            for (int i = 0; i < 21; ++i)
                x2P[(o >> 1) * 162 + ppad(28 + i) * 2 + (o & 1)] = fmaxf(fold2(a[i]), 0.0f);
        }
    }
    __syncthreads();

    // ---- 5: build v_first plane at x2P cp64 ----
    if (tid < 162) x2P[64 * 162 + tid] = 0.0f;
    __syncthreads();
    if (tid == 0) {
        int v = first_vertex[s];                 // [0,48]
        x2P[64 * 162 + ppad(v) * 2 + 0] = 1.0f;  // (v_first, 0) pair
    }
    __syncthreads();

    // ---- 6: const-gate precompute: gxc = bias_g0 + conv(x2P cps0..64; cx0) ----
    {
        const float bg0 = bcx0[tid] + bch0[tid];
        const unsigned long long binit = pack2(bg0, 0.0f);
        {
            unsigned long long a[28];
#pragma unroll
            for (int i = 0; i < 28; ++i) a[i] = binit;
            conv_pair<4, 0, 256>(g_p_cx0, 65, x2P, tid, a);
#pragma unroll
            for (int i = 0; i < 28; ++i) gxc[tid * 49 + i] = fold2(a[i]);
        }
        {
            unsigned long long a[21];
#pragma unroll
            for (int i = 0; i < 21; ++i) a[i] = pack2(0.0f, 0.0f);
            conv_pair<3, 4, 256>(g_p_cx0, 65, x2P, tid, a);
#pragma unroll
            for (int i = 0; i < 21; ++i) gxc[tid * 49 + 28 + i] = bg0 + fold2(a[i]);
        }
    }
    __syncthreads();

    // ---- 7: zero h0,h1,c0,c1 (x2P dead) + vtxP; init v_p1 = v_first one-hot ----
    for (int i = tid; i < SM_G; i += 256) sm[i] = 0.0f;
    if (tid < 162) vtxP[tid] = 0.0f;
    __syncthreads();
    if (tid == 0) {
        int v = first_vertex[s];
        vtxP[ppad(v) * 2 + 1] = 1.0f;            // (v_p2, v_p1): hi lane = v_p1
    }
    __syncthreads();

    const float bias_g1 = bcx1[tid] + bch1[tid];
    const float2* cx0_dyn = g_p_cx0 + 65 * 9 * 256;   // dynamic (v_p2, v_p1) pair weights
    const int warp = tid >> 5, lane = tid & 31;

    for (int t = 0; t < STEPS; ++t) {
        // ---- layer0 gates: gxc + conv(vtxP; cx0_dyn) + conv(h0P; ch0) ----
        {
            unsigned long long a[28];
#pragma unroll
            for (int i = 0; i < 28; ++i) a[i] = pack2(gxc[tid * 49 + i], 0.0f);
            conv_pair<4, 0, 256>(cx0_dyn, 1, vtxP, tid, a);
            conv_pair<4, 0, 256>(g_p_ch0, 32, h0P, tid, a);
#pragma unroll
            for (int i = 0; i < 28; ++i) gsm[tid * 49 + i] = fold2(a[i]);
        }
        {
            unsigned long long a[21];
#pragma unroll
            for (int i = 0; i < 21; ++i) a[i] = pack2(gxc[tid * 49 + 28 + i], 0.0f);
            conv_pair<3, 4, 256>(cx0_dyn, 1, vtxP, tid, a);
            conv_pair<3, 4, 256>(g_p_ch0, 32, h0P, tid, a);
#pragma unroll
            for (int i = 0; i < 21; ++i) gsm[tid * 49 + 28 + i] = fold2(a[i]);
        }
        __syncthreads();

        // ---- LSTM0 ----
        for (int i = tid; i < 3136; i += 256) {
            int c = i / 49, p = i - c * 49;
            float ig = sigm(gsm[c * 49 + p]);
            float fg = sigm(gsm[(c + 64) * 49 + p]);
            float gg = tanhf(gsm[(c + 128) * 49 + p]);
            float og = sigm(gsm[(c + 192) * 49 + p]);
            float cy = fg * c0s[i] + ig * gg;
            c0s[i] = cy;
            h0P[(c >> 1) * 162 + ppad(p) * 2 + (c & 1)] = og * tanhf(cy);
        }
        __syncthreads();

        // ---- layer1 gates: conv(h0P; cx1) + conv(h1P; ch1) ----
        {
            unsigned long long a[28];
            const unsigned long long binit = pack2(bias_g1, 0.0f);
#pragma unroll
            for (int i = 0; i < 28; ++i) a[i] = binit;
            conv_pair<4, 0, 256>(g_p_cx1, 32, h0P, tid, a);
            conv_pair<4, 0, 256>(g_p_ch1, 32, h1P, tid, a);
#pragma unroll
            for (int i = 0; i < 28; ++i) gsm[tid * 49 + i] = fold2(a[i]);
        }
        {
            unsigned long long a[21];
            const unsigned long long binit = pack2(bias_g1, 0.0f);
#pragma unroll
            for (int i = 0; i < 21; ++i) a[i] = binit;
            conv_pair<3, 4, 256>(g_p_cx1, 32, h0P, tid, a);
            conv_pair<3, 4, 256>(g_p_ch1, 32, h1P, tid, a);
#pragma unroll
            for (int i = 0; i < 21; ++i) gsm[tid * 49 + 28 + i] = fold2(a[i]);
        }
        __syncthreads();

        // ---- LSTM1 ----
        for (int i = tid; i < 3136; i += 256) {
            int c = i / 49, p = i - c * 49;
            float ig = sigm(gsm[c * 49 + p]);
            float fg = sigm(gsm[(c + 64) * 49 + p]);
            float gg = tanhf(gsm[(c + 128) * 49 + p]);
            float og = sigm(gsm[(c + 192) * 49 + p]);
            float cy = fg * c1s[i] + ig * gg;
            c1s[i] = cy;
            h1P[(c >> 1) * 162 + ppad(p) * 2 + (c & 1)] = og * tanhf(cy);
        }
        __syncthreads();

        // ---- fc: logits[50] ----
        for (int o = warp; o < 50; o += 8) {
            float ssum = 0.0f;
            const float* wr = fcw + o * 3136;
            int c = 0, p = lane;
            for (int j = lane; j < 3136; j += 32) {
                ssum += wr[j] * h1P[(c >> 1) * 162 + ppad(p) * 2 + (c & 1)];
                p += 32;
                if (p >= 49) { p -= 49; ++c; }
            }
#pragma unroll
            for (int d = 16; d; d >>= 1) ssum += __shfl_down_sync(0xffffffffu, ssum, d);
            if (lane == 0) lg[o] = ssum + fcb[o];
        }
        __syncthreads();

        // ---- emit + argmax (first max wins) ----
        if (tid < 50) out[((size_t)s * STEPS + t) * 50 + tid] = lg[tid];
        if (tid == 0) {
            int best = 0;
            float bv = lg[0];
#pragma unroll 1
            for (int o2 = 1; o2 < 50; ++o2) {
                float v = lg[o2];
                if (v > bv) { bv = v; best = o2; }
            }
            *predp = best;
        }
        __syncthreads();

        // ---- feedback: (v_p2, v_p1) <- (v_p1, one_hot(pred)); class 49 -> zeros ----
        {
            int pr = *predp;
            if (tid < 49) {
                int a2 = ppad(tid) * 2;
                vtxP[a2 + 0] = vtxP[a2 + 1];
                vtxP[a2 + 1] = (pr == tid) ? 1.0f : 0.0f;
            }
        }
        __syncthreads();
    }
}

extern "C" void kernel_launch(void* const* d_in, const int* in_sizes, int n_in,
                              void* d_out, int out_size)
{
    const float* x    = (const float*)d_in[0];
    const int*   fv   = (const int*)  d_in[1];
    const float* w0   = (const float*)d_in[2];
    const float* b0   = (const float*)d_in[3];
    const float* w1   = (const float*)d_in[4];
    const float* b1   = (const float*)d_in[5];
    const float* wcx0 = (const float*)d_in[6];
    const float* bcx0 = (const float*)d_in[7];
    const float* wch0 = (const float*)d_in[8];
    const float* bch0 = (const float*)d_in[9];
    const float* wcx1 = (const float*)d_in[10];
    const float* bcx1 = (const float*)d_in[11];
    const float* wch1 = (const float*)d_in[12];
    const float* bch1 = (const float*)d_in[13];
    const float* fcw  = (const float*)d_in[14];
    const float* fcb  = (const float*)d_in[15];
    float* out = (float*)d_out;

    const int n = in_sizes[1];  // batch

    const int total = 128 * 9 * 128 + 64 * 9 * 128 + 66 * 9 * 256 + 3 * 32 * 9 * 256;
    pack_weights<<<(total + 255) / 256, 256>>>(w0, w1, wcx0, wch0, wcx1, wch1);

    const int smem_bytes = SMEM_FLOATS * 4;
    cudaFuncSetAttribute(polyrnn_main, cudaFuncAttributeMaxDynamicSharedMemorySize, smem_bytes);
    polyrnn_main<<<n, 256, smem_bytes>>>(x, fv, b0, b1, bcx0, bch0, bcx1, bch1, fcw, fcb, out);
}

// round 9
// speedup vs baseline: 1.6814x; 1.0505x over previous
#include <cuda_runtime.h>
#include <math.h>

#define STEPS 9

// ---------------- packed pair weights (device globals; no allocation) ----
// layout: [(cpair*9 + k) * O + o] as float2
__device__ float2 g_p_conv0[128 * 9 * 128];  // C=256 -> 128 cp, O=128
__device__ float2 g_p_conv1[ 64 * 9 * 128];  // C=128 -> 64 cp,  O=128
// cx0 cp order: cp0..63 = x channel pairs; cp64 = (ch130 v_first, 0); cp65 = (v_p2, v_p1)
__device__ float2 g_p_cx0 [ 66 * 9 * 256];
__device__ float2 g_p_ch0 [ 32 * 9 * 256];
__device__ float2 g_p_cx1 [ 32 * 9 * 256];
__device__ float2 g_p_ch1 [ 32 * 9 * 256];

__global__ void pack_weights(const float* __restrict__ w0, const float* __restrict__ w1,
                             const float* __restrict__ wcx0, const float* __restrict__ wch0,
                             const float* __restrict__ wcx1, const float* __restrict__ wch1)
{
    int i = blockIdx.x * blockDim.x + threadIdx.x;
    const int s0 = 128 * 9 * 128, s1 = 64 * 9 * 128, s2 = 66 * 9 * 256, s3 = 32 * 9 * 256;
    if (i < s0) {
        int o = i % 128, ck = i / 128, cp = ck / 9, k = ck % 9;
        g_p_conv0[i] = make_float2(w0[(o * 256 + 2 * cp) * 9 + k],
                                   w0[(o * 256 + 2 * cp + 1) * 9 + k]);
        return;
    }
    i -= s0;
    if (i < s1) {
        int o = i % 128, ck = i / 128, cp = ck / 9, k = ck % 9;
        g_p_conv1[i] = make_float2(w1[(o * 128 + 2 * cp) * 9 + k],
                                   w1[(o * 128 + 2 * cp + 1) * 9 + k]);
        return;
    }
    i -= s1;
    if (i < s2) {
        int o = i % 256, ck = i / 256, cp = ck / 9, k = ck % 9;
        float a, b;
        if (cp < 64)      { a = wcx0[(o * 131 + 2 * cp) * 9 + k];
                            b = wcx0[(o * 131 + 2 * cp + 1) * 9 + k]; }
        else if (cp == 64){ a = wcx0[(o * 131 + 130) * 9 + k]; b = 0.0f; }
        else              { a = wcx0[(o * 131 + 128) * 9 + k];
                            b = wcx0[(o * 131 + 129) * 9 + k]; }
        g_p_cx0[i] = make_float2(a, b);
        return;
    }
    i -= s2;
    if (i < s3) {
        int o = i % 256, ck = i / 256, cp = ck / 9, k = ck % 9;
        g_p_ch0[i] = make_float2(wch0[(o * 64 + 2 * cp) * 9 + k],
                                 wch0[(o * 64 + 2 * cp + 1) * 9 + k]);
        return;
    }
    i -= s3;
    if (i < s3) {
        int o = i % 256, ck = i / 256, cp = ck / 9, k = ck % 9;
        g_p_cx1[i] = make_float2(wcx1[(o * 64 + 2 * cp) * 9 + k],
                                 wcx1[(o * 64 + 2 * cp + 1) * 9 + k]);
        return;
    }
    i -= s3;
    if (i < s3) {
        int o = i % 256, ck = i / 256, cp = ck / 9, k = ck % 9;
        g_p_ch1[i] = make_float2(wch1[(o * 64 + 2 * cp) * 9 + k],
                                 wch1[(o * 64 + 2 * cp + 1) * 9 + k]);
        return;
    }
}

// ---------------- packed fp32x2 helpers ----------------
__device__ __forceinline__ void ffma2(unsigned long long& d, unsigned long long a,
                                      unsigned long long b)
{
    asm("fma.rn.f32x2 %0, %1, %2, %0;" : "+l"(d) : "l"(a), "l"(b));
}
__device__ __forceinline__ unsigned long long pack2(float lo, float hi)
{
    unsigned long long r;
    asm("mov.b64 %0, {%1, %2};" : "=l"(r) : "f"(lo), "f"(hi));
    return r;
}
__device__ __forceinline__ float fold2(unsigned long long v)
{
    float lo, hi;
    asm("mov.b64 {%0, %1}, %2;" : "=f"(lo), "=f"(hi) : "l"(v));
    return lo + hi;
}
// padded pair-plane pixel address (floats): rows padded to 10 u64 (20 floats)
__device__ __forceinline__ int pidx(int p)
{
    return ((p / 7 + 1) * 10 + (p % 7) + 1) * 2;
}
__device__ __forceinline__ float sigm(float v) { return 1.0f / (1.0f + expf(-v)); }

// 3x3 SAME conv over channel-pair-interleaved padded planes (u64 = float pair).
// plane: [cp][9 rows x 10 u64]; row stride 10 u64 (16B-aligned rows -> LDS.128).
// Input-row-major: each input row loaded ONCE per cp (1 row live = 18 regs),
// applied to every output row it feeds (ky = ri - ry, compile-time resolved).
// Per-acc term order: (ky 0,1,2)x(kx 0,1,2) per cp — identical to prior rounds.
// Thread owns out-channel o, output rows [R0, R0+NR) x all 7 cols.
template <int NR, int R0, int OS>
__device__ __forceinline__ void conv_rm(const float2* __restrict__ W, const int CP,
                                        const float* __restrict__ plane,
                                        const int o, unsigned long long* acc)
{
    const unsigned long long* pb = (const unsigned long long*)plane + R0 * 10;
    const unsigned long long* wptr = (const unsigned long long*)W + o;

    for (int cp = 0; cp < CP; ++cp) {
        unsigned long long wA[9];
#pragma unroll
        for (int k = 0; k < 9; ++k) wA[k] = __ldg(wptr + k * OS);

#pragma unroll
        for (int ri = 0; ri < NR + 2; ++ri) {          // input row R0 + ri
            unsigned long long row[9];
            const ulonglong2* rp = (const ulonglong2*)(pb + ri * 10);
#pragma unroll
            for (int j = 0; j < 4; ++j) {
                ulonglong2 q = rp[j];
                row[2 * j] = q.x;
                row[2 * j + 1] = q.y;
            }
            row[8] = (pb + ri * 10)[8];
#pragma unroll
            for (int ry = 0; ry < NR; ++ry) {
                const int ky = ri - ry;
                if (ky >= 0 && ky < 3) {
#pragma unroll
                    for (int kx = 0; kx < 3; ++kx) {
                        const unsigned long long wv = wA[ky * 3 + kx];
#pragma unroll
                        for (int x = 0; x < 7; ++x)
                            ffma2(acc[ry * 7 + x], wv, row[x + kx]);
                    }
                }
            }
        }
        pb += 90;
        wptr += 9 * OS;
    }
}

// ---------------- SMEM layout (floats; planes = 180 floats/cp) ----------------
//   h0P @ 0     : 32*180 = 5760     h1P @ 5760 : 5760
//   c0  @ 11520 : 3136              c1  @ 14656: 3136
//   gsm @ 17792 : 12544             gxc @ 30336: 12544
//   vtxP@ 42880 : 180               lg  @ 43060: 50 ; pred @ 43112
// phase A overlays: xin @ 0 (128*180=23040), xoutP @ 30336 (64*180=11520),
//                   x2P @ 0 (65*180=11700; xin-geometry => borders stay 0)
#define SM_H0   0
#define SM_H1   5760
#define SM_C0   11520
#define SM_C1   14656
#define SM_G    17792
#define SM_GXC  30336
#define SM_VTX  42880
#define SM_LG   43060
#define SM_PRED 43112
#define SMEM_FLOATS 43120

#define NT 512

__global__ __launch_bounds__(NT, 1)
void polyrnn_main(const float* __restrict__ x, const int* __restrict__ first_vertex,
                  const float* __restrict__ b0, const float* __restrict__ b1,
                  const float* __restrict__ bcx0, const float* __restrict__ bch0,
                  const float* __restrict__ bcx1, const float* __restrict__ bch1,
                  const float* __restrict__ fcw, const float* __restrict__ fcb,
                  float* __restrict__ out)
{
    extern __shared__ float sm[];
    float* h0P   = sm + SM_H0;
    float* h1P   = sm + SM_H1;
    float* c0s   = sm + SM_C0;
    float* c1s   = sm + SM_C1;
    float* gsm   = sm + SM_G;
    float* gxc   = sm + SM_GXC;
    float* vtxP  = sm + SM_VTX;
    float* lg    = sm + SM_LG;
    int*   predp = (int*)(sm + SM_PRED);
    float* xin   = sm;            // phase A
    float* xoutP = sm + SM_GXC;   // phase A
    float* x2P   = sm;            // phase A

    const int s   = blockIdx.x;
    const int tid = threadIdx.x;

    // ---- 1: zero xin + xoutP regions (borders must be 0) ----
    for (int i = tid; i < 23040; i += NT) sm[i] = 0.0f;
    for (int i = tid; i < 11520; i += NT) xoutP[i] = 0.0f;
    __syncthreads();

    // ---- 2: load x into pair-interleaved padded planes ----
    const float* xs = x + (size_t)s * (256 * 49);
    for (int i = tid; i < 256 * 49; i += NT) {
        int c = i / 49, p = i % 49;
        xin[(c >> 1) * 180 + pidx(p) + (c & 1)] = xs[i];
    }
    __syncthreads();

    // ---- 3: conv0 (256->128) + ReLU -> xoutP ; 4 row-groups x 128 channels ----
    {
        const int o = tid & 127, q = tid >> 7;  // q: row group (2,2,2,1 rows)
        const unsigned long long binit = pack2(b0[o], 0.0f);
        unsigned long long a[14];
#pragma unroll
        for (int i = 0; i < 14; ++i) a[i] = binit;
        if (q == 0)      conv_rm<2, 0, 128>(g_p_conv0, 128, xin, o, a);
        else if (q == 1) conv_rm<2, 2, 128>(g_p_conv0, 128, xin, o, a);
        else if (q == 2) conv_rm<2, 4, 128>(g_p_conv0, 128, xin, o, a);
        else             conv_rm<1, 6, 128>(g_p_conv0, 128, xin, o, a);
        const int nr = (q == 3) ? 1 : 2, r0 = (q == 3) ? 6 : 2 * q;
        for (int lr = 0; lr < nr; ++lr)
#pragma unroll
            for (int xq = 0; xq < 7; ++xq)
                xoutP[(o >> 1) * 180 + pidx((r0 + lr) * 7 + xq) + (o & 1)] =
                    fmaxf(fold2(a[lr * 7 + xq]), 0.0f);
    }
    __syncthreads();

    // ---- 4: conv1 (128->128) + ReLU -> x2P cps 0..63 ----
    {
        const int o = tid & 127, q = tid >> 7;
        const unsigned long long binit = pack2(b1[o], 0.0f);
        unsigned long long a[14];
#pragma unroll
        for (int i = 0; i < 14; ++i) a[i] = binit;
        if (q == 0)      conv_rm<2, 0, 128>(g_p_conv1, 64, xoutP, o, a);
        else if (q == 1) conv_rm<2, 2, 128>(g_p_conv1, 64, xoutP, o, a);
        else if (q == 2) conv_rm<2, 4, 128>(g_p_conv1, 64, xoutP, o, a);
        else             conv_rm<1, 6, 128>(g_p_conv1, 64, xoutP, o, a);
        const int nr = (q == 3) ? 1 : 2, r0 = (q == 3) ? 6 : 2 * q;
        for (int lr = 0; lr < nr; ++lr)
#pragma unroll
            for (int xq = 0; xq < 7; ++xq)
                x2P[(o >> 1) * 180 + pidx((r0 + lr) * 7 + xq) + (o & 1)] =
                    fmaxf(fold2(a[lr * 7 + xq]), 0.0f);
    }
    __syncthreads();

    // ---- 5: build v_first plane at x2P cp64 ----
    if (tid < 180) x2P[64 * 180 + tid] = 0.0f;
    __syncthreads();
    if (tid == 0) {
        int v = first_vertex[s];                 // [0,48]
        x2P[64 * 180 + pidx(v) + 0] = 1.0f;      // (v_first, 0) pair
    }
    __syncthreads();

    // ---- 6: const-gate precompute: gxc = bias_g0 + conv(x2P cps0..64; cx0) ----
    {
        const int o = tid & 255, rh = tid >> 8;
        const float bg0 = bcx0[o] + bch0[o];
        if (rh == 0) {
            unsigned long long a[28];
            const unsigned long long binit = pack2(bg0, 0.0f);
#pragma unroll
            for (int i = 0; i < 28; ++i) a[i] = binit;
            conv_rm<4, 0, 256>(g_p_cx0, 65, x2P, o, a);
#pragma unroll
            for (int i = 0; i < 28; ++i) gxc[o * 49 + i] = fold2(a[i]);
        } else {
            unsigned long long a[21];
#pragma unroll
            for (int i = 0; i < 21; ++i) a[i] = pack2(0.0f, 0.0f);
            conv_rm<3, 4, 256>(g_p_cx0, 65, x2P, o, a);
#pragma unroll
            for (int i = 0; i < 21; ++i) gxc[o * 49 + 28 + i] = bg0 + fold2(a[i]);
        }
    }
    __syncthreads();

    // ---- 7: zero h0,h1,c0,c1 (x2P dead) + vtxP; init v_p1 = v_first one-hot ----
    for (int i = tid; i < SM_G; i += NT) sm[i] = 0.0f;
    if (tid < 180) vtxP[tid] = 0.0f;
    __syncthreads();
    if (tid == 0) {
        int v = first_vertex[s];
        vtxP[pidx(v) + 1] = 1.0f;                // (v_p2, v_p1): hi lane = v_p1
    }
    __syncthreads();

    const int o_g = tid & 255;
    const int rh  = tid >> 8;                    // row half: 0 -> rows 0-3, 1 -> rows 4-6
    const float bias_g1 = bcx1[o_g] + bch1[o_g];
    const float2* cx0_dyn = g_p_cx0 + 65 * 9 * 256;   // dynamic (v_p2, v_p1) pair weights
    const int warp = tid >> 5, lane = tid & 31;

    for (int t = 0; t < STEPS; ++t) {
        // ---- layer0 gates: gxc + conv(vtxP; cx0_dyn) + conv(h0P; ch0) ----
        if (rh == 0) {
            unsigned long long a[28];
#pragma unroll
            for (int i = 0; i < 28; ++i) a[i] = pack2(gxc[o_g * 49 + i], 0.0f);
            conv_rm<4, 0, 256>(cx0_dyn, 1, vtxP, o_g, a);
            conv_rm<4, 0, 256>(g_p_ch0, 32, h0P, o_g, a);
#pragma unroll
            for (int i = 0; i < 28; ++i) gsm[o_g * 49 + i] = fold2(a[i]);
        } else {
            unsigned long long a[21];
#pragma unroll
            for (int i = 0; i < 21; ++i) a[i] = pack2(gxc[o_g * 49 + 28 + i], 0.0f);
            conv_rm<3, 4, 256>(cx0_dyn, 1, vtxP, o_g, a);
            conv_rm<3, 4, 256>(g_p_ch0, 32, h0P, o_g, a);
#pragma unroll
            for (int i = 0; i < 21; ++i) gsm[o_g * 49 + 28 + i] = fold2(a[i]);
        }
        __syncthreads();

        // ---- LSTM0 ----
        for (int i = tid; i < 3136; i += NT) {
            int c = i / 49, p = i - c * 49;
            float ig = sigm(gsm[c * 49 + p]);
            float fg = sigm(gsm[(c + 64) * 49 + p]);
            float gg = tanhf(gsm[(c + 128) * 49 + p]);
            float og = sigm(gsm[(c + 192) * 49 + p]);
            float cy = fg * c0s[i] + ig * gg;
            c0s[i] = cy;
            h0P[(c >> 1) * 180 + pidx(p) + (c & 1)] = og * tanhf(cy);
        }
        __syncthreads();

        // ---- layer1 gates: conv(h0P; cx1) + conv(h1P; ch1) ----
        if (rh == 0) {
            unsigned long long a[28];
            const unsigned long long binit = pack2(bias_g1, 0.0f);
#pragma unroll
            for (int i = 0; i < 28; ++i) a[i] = binit;
            conv_rm<4, 0, 256>(g_p_cx1, 32, h0P, o_g, a);
            conv_rm<4, 0, 256>(g_p_ch1, 32, h1P, o_g, a);
#pragma unroll
            for (int i = 0; i < 28; ++i) gsm[o_g * 49 + i] = fold2(a[i]);
        } else {
            unsigned long long a[21];
            const unsigned long long binit = pack2(bias_g1, 0.0f);
#pragma unroll
            for (int i = 0; i < 21; ++i) a[i] = binit;
            conv_rm<3, 4, 256>(g_p_cx1, 32, h0P, o_g, a);
            conv_rm<3, 4, 256>(g_p_ch1, 32, h1P, o_g, a);
#pragma unroll
            for (int i = 0; i < 21; ++i) gsm[o_g * 49 + 28 + i] = fold2(a[i]);
        }
        __syncthreads();

        // ---- LSTM1 ----
        for (int i = tid; i < 3136; i += NT) {
            int c = i / 49, p = i - c * 49;
            float ig = sigm(gsm[c * 49 + p]);
            float fg = sigm(gsm[(c + 64) * 49 + p]);
            float gg = tanhf(gsm[(c + 128) * 49 + p]);
            float og = sigm(gsm[(c + 192) * 49 + p]);
            float cy = fg * c1s[i] + ig * gg;
            c1s[i] = cy;
            h1P[(c >> 1) * 180 + pidx(p) + (c & 1)] = og * tanhf(cy);
        }
        __syncthreads();

        // ---- fc: logits[50] over 16 warps ----
        for (int o = warp; o < 50; o += 16) {
            float ssum = 0.0f;
            const float* wr = fcw + o * 3136;
            int c = 0, p = lane;
            for (int j = lane; j < 3136; j += 32) {
                ssum += wr[j] * h1P[(c >> 1) * 180 + pidx(p) + (c & 1)];
                p += 32;
                if (p >= 49) { p -= 49; ++c; }
            }
#pragma unroll
            for (int d = 16; d; d >>= 1) ssum += __shfl_down_sync(0xffffffffu, ssum, d);
            if (lane == 0) lg[o] = ssum + fcb[o];
        }
        __syncthreads();

        // ---- emit + argmax (first max wins) ----
        if (tid < 50) out[((size_t)s * STEPS + t) * 50 + tid] = lg[tid];
        if (tid == 0) {
            int best = 0;
            float bv = lg[0];
#pragma unroll 1
            for (int o2 = 1; o2 < 50; ++o2) {
                float v = lg[o2];
                if (v > bv) { bv = v; best = o2; }
            }
            *predp = best;
        }
        __syncthreads();

        // ---- feedback: (v_p2, v_p1) <- (v_p1, one_hot(pred)); class 49 -> zeros ----
        {
            int pr = *predp;
            if (tid < 49) {
                int a2 = pidx(tid);
                vtxP[a2 + 0] = vtxP[a2 + 1];
                vtxP[a2 + 1] = (pr == tid) ? 1.0f : 0.0f;
            }
        }
        __syncthreads();
    }
}

extern "C" void kernel_launch(void* const* d_in, const int* in_sizes, int n_in,
                              void* d_out, int out_size)
{
    const float* x    = (const float*)d_in[0];
    const int*   fv   = (const int*)  d_in[1];
    const float* w0   = (const float*)d_in[2];
    const float* b0   = (const float*)d_in[3];
    const float* w1   = (const float*)d_in[4];
    const float* b1   = (const float*)d_in[5];
    const float* wcx0 = (const float*)d_in[6];
    const float* bcx0 = (const float*)d_in[7];
    const float* wch0 = (const float*)d_in[8];
    const float* bch0 = (const float*)d_in[9];
    const float* wcx1 = (const float*)d_in[10];
    const float* bcx1 = (const float*)d_in[11];
    const float* wch1 = (const float*)d_in[12];
    const float* bch1 = (const float*)d_in[13];
    const float* fcw  = (const float*)d_in[14];
    const float* fcb  = (const float*)d_in[15];
    float* out = (float*)d_out;

    const int n = in_sizes[1];  // batch

    const int total = 128 * 9 * 128 + 64 * 9 * 128 + 66 * 9 * 256 + 3 * 32 * 9 * 256;
    pack_weights<<<(total + 255) / 256, 256>>>(w0, w1, wcx0, wch0, wcx1, wch1);

    const int smem_bytes = SMEM_FLOATS * 4;
    cudaFuncSetAttribute(polyrnn_main, cudaFuncAttributeMaxDynamicSharedMemorySize, smem_bytes);
    polyrnn_main<<<n, NT, smem_bytes>>>(x, fv, b0, b1, bcx0, bch0, bcx1, bch1, fcw, fcb, out);
}

// round 10
// speedup vs baseline: 1.7105x; 1.0173x over previous
#include <cuda_runtime.h>
#include <math.h>

#define STEPS 9

// ---------------- packed pair weights (device globals; no allocation) ----
// layout: [(cpair*9 + k) * O + o] as float2
__device__ float2 g_p_conv0[128 * 9 * 128];  // C=256 -> 128 cp, O=128
__device__ float2 g_p_conv1[ 64 * 9 * 128];  // C=128 -> 64 cp,  O=128
// cx0 cp order: cp0..63 = x channel pairs; cp64 = (ch130 v_first, 0); cp65 = (v_p2, v_p1)
__device__ float2 g_p_cx0 [ 66 * 9 * 256];
__device__ float2 g_p_ch0 [ 32 * 9 * 256];
__device__ float2 g_p_cx1 [ 32 * 9 * 256];
__device__ float2 g_p_ch1 [ 32 * 9 * 256];

__global__ void pack_weights(const float* __restrict__ w0, const float* __restrict__ w1,
                             const float* __restrict__ wcx0, const float* __restrict__ wch0,
                             const float* __restrict__ wcx1, const float* __restrict__ wch1)
{
    int i = blockIdx.x * blockDim.x + threadIdx.x;
    const int s0 = 128 * 9 * 128, s1 = 64 * 9 * 128, s2 = 66 * 9 * 256, s3 = 32 * 9 * 256;
    if (i < s0) {
        int o = i % 128, ck = i / 128, cp = ck / 9, k = ck % 9;
        g_p_conv0[i] = make_float2(w0[(o * 256 + 2 * cp) * 9 + k],
                                   w0[(o * 256 + 2 * cp + 1) * 9 + k]);
        return;
    }
    i -= s0;
    if (i < s1) {
        int o = i % 128, ck = i / 128, cp = ck / 9, k = ck % 9;
        g_p_conv1[i] = make_float2(w1[(o * 128 + 2 * cp) * 9 + k],
                                   w1[(o * 128 + 2 * cp + 1) * 9 + k]);
        return;
    }
    i -= s1;
    if (i < s2) {
        int o = i % 256, ck = i / 256, cp = ck / 9, k = ck % 9;
        float a, b;
        if (cp < 64)      { a = wcx0[(o * 131 + 2 * cp) * 9 + k];
                            b = wcx0[(o * 131 + 2 * cp + 1) * 9 + k]; }
        else if (cp == 64){ a = wcx0[(o * 131 + 130) * 9 + k]; b = 0.0f; }
        else              { a = wcx0[(o * 131 + 128) * 9 + k];
                            b = wcx0[(o * 131 + 129) * 9 + k]; }
        g_p_cx0[i] = make_float2(a, b);
        return;
    }
    i -= s2;
    if (i < s3) {
        int o = i % 256, ck = i / 256, cp = ck / 9, k = ck % 9;
        g_p_ch0[i] = make_float2(wch0[(o * 64 + 2 * cp) * 9 + k],
                                 wch0[(o * 64 + 2 * cp + 1) * 9 + k]);
        return;
    }
    i -= s3;
    if (i < s3) {
        int o = i % 256, ck = i / 256, cp = ck / 9, k = ck % 9;
        g_p_cx1[i] = make_float2(wcx1[(o * 64 + 2 * cp) * 9 + k],
                                 wcx1[(o * 64 + 2 * cp + 1) * 9 + k]);
        return;
    }
    i -= s3;
    if (i < s3) {
        int o = i % 256, ck = i / 256, cp = ck / 9, k = ck % 9;
        g_p_ch1[i] = make_float2(wch1[(o * 64 + 2 * cp) * 9 + k],
                                 wch1[(o * 64 + 2 * cp + 1) * 9 + k]);
        return;
    }
}

// ---------------- packed fp32x2 helpers ----------------
__device__ __forceinline__ void ffma2(unsigned long long& d, unsigned long long a,
                                      unsigned long long b)
{
    asm("fma.rn.f32x2 %0, %1, %2, %0;" : "+l"(d) : "l"(a), "l"(b));
}
__device__ __forceinline__ unsigned long long pack2(float lo, float hi)
{
    unsigned long long r;
    asm("mov.b64 %0, {%1, %2};" : "=l"(r) : "f"(lo), "f"(hi));
    return r;
}
__device__ __forceinline__ float fold2(unsigned long long v)
{
    float lo, hi;
    asm("mov.b64 {%0, %1}, %2;" : "=f"(lo), "=f"(hi) : "l"(v));
    return lo + hi;
}
// padded pair-plane pixel address (floats): rows padded to 10 u64 (20 floats)
__device__ __forceinline__ int pidx(int p)
{
    return ((p / 7 + 1) * 10 + (p % 7) + 1) * 2;
}
__device__ __forceinline__ float sigm(float v) { return 1.0f / (1.0f + expf(-v)); }

// 3x3 SAME conv over channel-pair-interleaved padded planes (u64 = float pair).
// plane: [cp][9 rows x 10 u64]; row stride 10 u64 (16B-aligned rows -> LDS.128).
// Input-row-major with ZERO-REGISTER weight software pipeline: tap trio ky is
// dead after input row ri = NR-1+ky, so the NEXT cp's trio is prefetched into
// the SAME registers right there — LDG issued ~1-2 row-iterations before use,
// covering L2 latency with no extra registers.
// Per-acc term order: (ky 0,1,2)x(kx 0,1,2) per cp — identical to prior rounds.
template <int NR, int R0, int OS>
__device__ __forceinline__ void conv_rm(const float2* __restrict__ W, const int CP,
                                        const float* __restrict__ plane,
                                        const int o, unsigned long long* acc)
{
    const unsigned long long* pb = (const unsigned long long*)plane + R0 * 10;
    const unsigned long long* wptr = (const unsigned long long*)W + o;

    unsigned long long wA[9];
#pragma unroll
    for (int k = 0; k < 9; ++k) wA[k] = __ldg(wptr + k * OS);

    for (int cp = 0; cp < CP; ++cp) {
        const unsigned long long* wnext = (cp + 1 < CP) ? wptr + 9 * OS : wptr;

#pragma unroll
        for (int ri = 0; ri < NR + 2; ++ri) {          // input row R0 + ri
            unsigned long long row[9];
            const ulonglong2* rp = (const ulonglong2*)(pb + ri * 10);
#pragma unroll
            for (int j = 0; j < 4; ++j) {
                ulonglong2 q = rp[j];
                row[2 * j] = q.x;
                row[2 * j + 1] = q.y;
            }
            row[8] = (pb + ri * 10)[8];
#pragma unroll
            for (int ky = 0; ky < 3; ++ky) {
                const int ry = ri - ky;
                if (ry >= 0 && ry < NR) {
#pragma unroll
                    for (int kx = 0; kx < 3; ++kx) {
                        const unsigned long long wv = wA[ky * 3 + kx];
#pragma unroll
                        for (int x = 0; x < 7; ++x)
                            ffma2(acc[ry * 7 + x], wv, row[x + kx]);
                    }
                }
            }
            // in-place prefetch of next cp's taps after each trio's last use
            if (ri == NR - 1) {
#pragma unroll
                for (int k = 0; k < 3; ++k) wA[k] = __ldg(wnext + k * OS);
            }
            if (ri == NR) {
#pragma unroll
                for (int k = 3; k < 6; ++k) wA[k] = __ldg(wnext + k * OS);
            }
            if (ri == NR + 1) {
#pragma unroll
                for (int k = 6; k < 9; ++k) wA[k] = __ldg(wnext + k * OS);
            }
        }
        pb += 90;
        wptr = wnext;
    }
}

// ---------------- SMEM layout (floats; planes = 180 floats/cp) ----------------
//   h0P @ 0     : 32*180 = 5760     h1P @ 5760 : 5760
//   c0  @ 11520 : 3136              c1  @ 14656: 3136
//   gsm @ 17792 : 256*50 = 12800    gxc @ 30592: 12544
//   vtxP@ 43136 : 180               lg  @ 43316: 50
// phase A overlays: xin @ 0 (128*180=23040), xoutP @ 30592 (64*180=11520),
//                   x2P @ 0 (65*180=11700)
#define SM_H0   0
#define SM_H1   5760
#define SM_C0   11520
#define SM_C1   14656
#define SM_G    17792
#define SM_GXC  30592
#define SM_VTX  43136
#define SM_LG   43316
#define SMEM_FLOATS 43368

#define NT 512

__global__ __launch_bounds__(NT, 1)
void polyrnn_main(const float* __restrict__ x, const int* __restrict__ first_vertex,
                  const float* __restrict__ b0, const float* __restrict__ b1,
                  const float* __restrict__ bcx0, const float* __restrict__ bch0,
                  const float* __restrict__ bcx1, const float* __restrict__ bch1,
                  const float* __restrict__ fcw, const float* __restrict__ fcb,
                  float* __restrict__ out)
{
    extern __shared__ float sm[];
    float* h0P   = sm + SM_H0;
    float* h1P   = sm + SM_H1;
    float* c0s   = sm + SM_C0;
    float* c1s   = sm + SM_C1;
    float* gsm   = sm + SM_G;
    float* gxc   = sm + SM_GXC;
    float* vtxP  = sm + SM_VTX;
    float* lg    = sm + SM_LG;
    float* xin   = sm;            // phase A
    float* xoutP = sm + SM_GXC;   // phase A
    float* x2P   = sm;            // phase A

    const int s   = blockIdx.x;
    const int tid = threadIdx.x;

    // ---- 1: zero xin + xoutP regions (borders must be 0) ----
    for (int i = tid; i < 23040; i += NT) sm[i] = 0.0f;
    for (int i = tid; i < 11520; i += NT) xoutP[i] = 0.0f;
    __syncthreads();

    // ---- 2: load x into pair-interleaved padded planes ----
    const float* xs = x + (size_t)s * (256 * 49);
    for (int i = tid; i < 256 * 49; i += NT) {
        int c = i / 49, p = i % 49;
        xin[(c >> 1) * 180 + pidx(p) + (c & 1)] = xs[i];
    }
    __syncthreads();

    // ---- 3: conv0 (256->128) + ReLU -> xoutP ; 4 row-groups x 128 channels ----
    {
        const int o = tid & 127, q = tid >> 7;  // q: row group (2,2,2,1 rows)
        const unsigned long long binit = pack2(b0[o], 0.0f);
        unsigned long long a[14];
#pragma unroll
        for (int i = 0; i < 14; ++i) a[i] = binit;
        if (q == 0)      conv_rm<2, 0, 128>(g_p_conv0, 128, xin, o, a);
        else if (q == 1) conv_rm<2, 2, 128>(g_p_conv0, 128, xin, o, a);
        else if (q == 2) conv_rm<2, 4, 128>(g_p_conv0, 128, xin, o, a);
        else             conv_rm<1, 6, 128>(g_p_conv0, 128, xin, o, a);
        const int nr = (q == 3) ? 1 : 2, r0 = (q == 3) ? 6 : 2 * q;
        for (int lr = 0; lr < nr; ++lr)
#pragma unroll
            for (int xq = 0; xq < 7; ++xq)
                xoutP[(o >> 1) * 180 + pidx((r0 + lr) * 7 + xq) + (o & 1)] =
                    fmaxf(fold2(a[lr * 7 + xq]), 0.0f);
    }
    __syncthreads();

    // ---- 4: conv1 (128->128) + ReLU -> x2P cps 0..63 ----
    {
        const int o = tid & 127, q = tid >> 7;
        const unsigned long long binit = pack2(b1[o], 0.0f);
        unsigned long long a[14];
#pragma unroll
        for (int i = 0; i < 14; ++i) a[i] = binit;
        if (q == 0)      conv_rm<2, 0, 128>(g_p_conv1, 64, xoutP, o, a);
        else if (q == 1) conv_rm<2, 2, 128>(g_p_conv1, 64, xoutP, o, a);
        else if (q == 2) conv_rm<2, 4, 128>(g_p_conv1, 64, xoutP, o, a);
        else             conv_rm<1, 6, 128>(g_p_conv1, 64, xoutP, o, a);
        const int nr = (q == 3) ? 1 : 2, r0 = (q == 3) ? 6 : 2 * q;
        for (int lr = 0; lr < nr; ++lr)
#pragma unroll
            for (int xq = 0; xq < 7; ++xq)
                x2P[(o >> 1) * 180 + pidx((r0 + lr) * 7 + xq) + (o & 1)] =
                    fmaxf(fold2(a[lr * 7 + xq]), 0.0f);
    }
    __syncthreads();

    // ---- 5: build v_first plane at x2P cp64 ----
    if (tid < 180) x2P[64 * 180 + tid] = 0.0f;
    __syncthreads();
    if (tid == 0) {
        int v = first_vertex[s];                 // [0,48]
        x2P[64 * 180 + pidx(v) + 0] = 1.0f;      // (v_first, 0) pair
    }
    __syncthreads();

    // ---- 6: const-gate precompute: gxc = bias_g0 + conv(x2P cps0..64; cx0) ----
    {
        const int o = tid & 255, rh2 = tid >> 8;
        const float bg0 = bcx0[o] + bch0[o];
        if (rh2 == 0) {
            unsigned long long a[28];
            const unsigned long long binit = pack2(bg0, 0.0f);
#pragma unroll
            for (int i = 0; i < 28; ++i) a[i] = binit;
            conv_rm<4, 0, 256>(g_p_cx0, 65, x2P, o, a);
#pragma unroll
            for (int i = 0; i < 28; ++i) gxc[o * 49 + i] = fold2(a[i]);
        } else {
            unsigned long long a[21];
#pragma unroll
            for (int i = 0; i < 21; ++i) a[i] = pack2(0.0f, 0.0f);
            conv_rm<3, 4, 256>(g_p_cx0, 65, x2P, o, a);
#pragma unroll
            for (int i = 0; i < 21; ++i) gxc[o * 49 + 28 + i] = bg0 + fold2(a[i]);
        }
    }
    __syncthreads();

    // ---- 7: zero h0,h1,c0,c1 (x2P dead) + vtxP; init v_p1 = v_first one-hot ----
    for (int i = tid; i < SM_G; i += NT) sm[i] = 0.0f;
    if (tid < 180) vtxP[tid] = 0.0f;
    __syncthreads();
    if (tid == 0) {
        int v = first_vertex[s];
        vtxP[pidx(v) + 1] = 1.0f;                // (v_p2, v_p1): hi lane = v_p1
    }
    __syncthreads();

    const int o_g = tid & 255;
    const int rh  = tid >> 8;                    // row half: 0 -> rows 0-3, 1 -> rows 4-6
    const float bias_g1 = bcx1[o_g] + bch1[o_g];
    const float2* cx0_dyn = g_p_cx0 + 65 * 9 * 256;   // dynamic (v_p2, v_p1) pair weights
    const int warp = tid >> 5, lane = tid & 31;

    for (int t = 0; t < STEPS; ++t) {
        // ---- layer0 gates: gxc + conv(vtxP; cx0_dyn) + conv(h0P; ch0) ----
        if (rh == 0) {
            unsigned long long a[28];
#pragma unroll
            for (int i = 0; i < 28; ++i) a[i] = pack2(gxc[o_g * 49 + i], 0.0f);
            conv_rm<4, 0, 256>(cx0_dyn, 1, vtxP, o_g, a);
            conv_rm<4, 0, 256>(g_p_ch0, 32, h0P, o_g, a);
#pragma unroll
            for (int i = 0; i < 14; ++i) {
                unsigned long long pv = pack2(fold2(a[2 * i]), fold2(a[2 * i + 1]));
                *(unsigned long long*)(gsm + o_g * 50 + 2 * i) = pv;
            }
        } else {
            unsigned long long a[21];
#pragma unroll
            for (int i = 0; i < 21; ++i) a[i] = pack2(gxc[o_g * 49 + 28 + i], 0.0f);
            conv_rm<3, 4, 256>(cx0_dyn, 1, vtxP, o_g, a);
            conv_rm<3, 4, 256>(g_p_ch0, 32, h0P, o_g, a);
#pragma unroll
            for (int i = 0; i < 10; ++i) {
                unsigned long long pv = pack2(fold2(a[2 * i]), fold2(a[2 * i + 1]));
                *(unsigned long long*)(gsm + o_g * 50 + 28 + 2 * i) = pv;
            }
            gsm[o_g * 50 + 48] = fold2(a[20]);
        }
        __syncthreads();

        // ---- LSTM0 ----
        for (int i = tid; i < 3136; i += NT) {
            int c = i / 49, p = i - c * 49;
            float ig = sigm(gsm[c * 50 + p]);
            float fg = sigm(gsm[(c + 64) * 50 + p]);
            float gg = tanhf(gsm[(c + 128) * 50 + p]);
            float og = sigm(gsm[(c + 192) * 50 + p]);
            float cy = fg * c0s[i] + ig * gg;
            c0s[i] = cy;
            h0P[(c >> 1) * 180 + pidx(p) + (c & 1)] = og * tanhf(cy);
        }
        __syncthreads();

        // ---- layer1 gates: conv(h0P; cx1) + conv(h1P; ch1) ----
        if (rh == 0) {
            unsigned long long a[28];
            const unsigned long long binit = pack2(bias_g1, 0.0f);
#pragma unroll
            for (int i = 0; i < 28; ++i) a[i] = binit;
            conv_rm<4, 0, 256>(g_p_cx1, 32, h0P, o_g, a);
            conv_rm<4, 0, 256>(g_p_ch1, 32, h1P, o_g, a);
#pragma unroll
            for (int i = 0; i < 14; ++i) {
                unsigned long long pv = pack2(fold2(a[2 * i]), fold2(a[2 * i + 1]));
                *(unsigned long long*)(gsm + o_g * 50 + 2 * i) = pv;
            }
        } else {
            unsigned long long a[21];
            const unsigned long long binit = pack2(bias_g1, 0.0f);
#pragma unroll
            for (int i = 0; i < 21; ++i) a[i] = binit;
            conv_rm<3, 4, 256>(g_p_cx1, 32, h0P, o_g, a);
            conv_rm<3, 4, 256>(g_p_ch1, 32, h1P, o_g, a);
#pragma unroll
            for (int i = 0; i < 10; ++i) {
                unsigned long long pv = pack2(fold2(a[2 * i]), fold2(a[2 * i + 1]));
                *(unsigned long long*)(gsm + o_g * 50 + 28 + 2 * i) = pv;
            }
            gsm[o_g * 50 + 48] = fold2(a[20]);
        }
        __syncthreads();

        // ---- LSTM1 ----
        for (int i = tid; i < 3136; i += NT) {
            int c = i / 49, p = i - c * 49;
            float ig = sigm(gsm[c * 50 + p]);
            float fg = sigm(gsm[(c + 64) * 50 + p]);
            float gg = tanhf(gsm[(c + 128) * 50 + p]);
            float og = sigm(gsm[(c + 192) * 50 + p]);
            float cy = fg * c1s[i] + ig * gg;
            c1s[i] = cy;
            h1P[(c >> 1) * 180 + pidx(p) + (c & 1)] = og * tanhf(cy);
        }
        __syncthreads();

        // ---- fc: logits[50] over 16 warps ----
        for (int o = warp; o < 50; o += 16) {
            float ssum = 0.0f;
            const float* wr = fcw + o * 3136;
            int c = 0, p = lane;
            for (int j = lane; j < 3136; j += 32) {
                ssum += wr[j] * h1P[(c >> 1) * 180 + pidx(p) + (c & 1)];
                p += 32;
                if (p >= 49) { p -= 49; ++c; }
            }
#pragma unroll
            for (int d = 16; d; d >>= 1) ssum += __shfl_down_sync(0xffffffffu, ssum, d);
            if (lane == 0) lg[o] = ssum + fcb[o];
        }
        __syncthreads();

        // ---- emit; fused argmax + feedback in warp 0 (first-max-wins) ----
        if (tid < 50) out[((size_t)s * STEPS + t) * 50 + tid] = lg[tid];
        if (warp == 0) {
            float bv = lg[lane];
            int bi = lane;
            float v2 = (lane < 18) ? lg[32 + lane] : -3.402823466e38f;
            if (v2 > bv) { bv = v2; bi = 32 + lane; }
#pragma unroll
            for (int d = 16; d; d >>= 1) {
                float ov = __shfl_down_sync(0xffffffffu, bv, d);
                int   oi = __shfl_down_sync(0xffffffffu, bi, d);
                if (ov > bv || (ov == bv && oi < bi)) { bv = ov; bi = oi; }
            }
            bi = __shfl_sync(0xffffffffu, bi, 0);
            // feedback: (v_p2, v_p1) <- (v_p1, one_hot(pred)); class 49 -> zeros
            for (int p4 = lane; p4 < 49; p4 += 32) {
                int a2 = pidx(p4);
                vtxP[a2 + 0] = vtxP[a2 + 1];
                vtxP[a2 + 1] = (bi == p4) ? 1.0f : 0.0f;
            }
        }
        __syncthreads();
    }
}

extern "C" void kernel_launch(void* const* d_in, const int* in_sizes, int n_in,
                              void* d_out, int out_size)
{
    const float* x    = (const float*)d_in[0];
    const int*   fv   = (const int*)  d_in[1];
    const float* w0   = (const float*)d_in[2];
    const float* b0   = (const float*)d_in[3];
    const float* w1   = (const float*)d_in[4];
    const float* b1   = (const float*)d_in[5];
    const float* wcx0 = (const float*)d_in[6];
    const float* bcx0 = (const float*)d_in[7];
    const float* wch0 = (const float*)d_in[8];
    const float* bch0 = (const float*)d_in[9];
    const float* wcx1 = (const float*)d_in[10];
    const float* bcx1 = (const float*)d_in[11];
    const float* wch1 = (const float*)d_in[12];
    const float* bch1 = (const float*)d_in[13];
    const float* fcw  = (const float*)d_in[14];
    const float* fcb  = (const float*)d_in[15];
    float* out = (float*)d_out;

    const int n = in_sizes[1];  // batch

    const int total = 128 * 9 * 128 + 64 * 9 * 128 + 66 * 9 * 256 + 3 * 32 * 9 * 256;
    pack_weights<<<(total + 255) / 256, 256>>>(w0, w1, wcx0, wch0, wcx1, wch1);

    const int smem_bytes = SMEM_FLOATS * 4;
    cudaFuncSetAttribute(polyrnn_main, cudaFuncAttributeMaxDynamicSharedMemorySize, smem_bytes);
    polyrnn_main<<<n, NT, smem_bytes>>>(x, fv, b0, b1, bcx0, bch0, bcx1, bch1, fcw, fcb, out);
}

// round 11
// speedup vs baseline: 1.8980x; 1.1096x over previous
#include <cuda_runtime.h>
#include <math.h>

#define STEPS 9
#define NBATCH 2048

// ---------------- packed pair weights (device globals; no allocation) ----
// layout: [(cpair*9 + k) * O + o] as float2
__device__ float2 g_p_conv0[128 * 9 * 128];  // C=256 -> 128 cp, O=128
__device__ float2 g_p_conv1[ 64 * 9 * 128];  // C=128 -> 64 cp,  O=128
// cx0 cp order: cp0..63 = x channel pairs; cp64 = (ch130 v_first, 0); cp65 = (v_p2, v_p1)
__device__ float2 g_p_cx0 [ 66 * 9 * 256];
__device__ float2 g_p_ch0 [ 32 * 9 * 256];
__device__ float2 g_p_cx1 [ 32 * 9 * 256];
__device__ float2 g_p_ch1 [ 32 * 9 * 256];
// per-sample scratch (moved out of smem to allow 2 CTAs/SM)
__device__ float g_gxc[(size_t)NBATCH * 12544];  // const gates, TRANSPOSED [i*256+o]
__device__ float g_c  [(size_t)NBATCH * 6272];   // c0 (3136) + c1 (3136)

__global__ void pack_weights(const float* __restrict__ w0, const float* __restrict__ w1,
                             const float* __restrict__ wcx0, const float* __restrict__ wch0,
                             const float* __restrict__ wcx1, const float* __restrict__ wch1)
{
    int i = blockIdx.x * blockDim.x + threadIdx.x;
    const int s0 = 128 * 9 * 128, s1 = 64 * 9 * 128, s2 = 66 * 9 * 256, s3 = 32 * 9 * 256;
    if (i < s0) {
        int o = i % 128, ck = i / 128, cp = ck / 9, k = ck % 9;
        g_p_conv0[i] = make_float2(w0[(o * 256 + 2 * cp) * 9 + k],
                                   w0[(o * 256 + 2 * cp + 1) * 9 + k]);
        return;
    }
    i -= s0;
    if (i < s1) {
        int o = i % 128, ck = i / 128, cp = ck / 9, k = ck % 9;
        g_p_conv1[i] = make_float2(w1[(o * 128 + 2 * cp) * 9 + k],
                                   w1[(o * 128 + 2 * cp + 1) * 9 + k]);
        return;
    }
    i -= s1;
    if (i < s2) {
        int o = i % 256, ck = i / 256, cp = ck / 9, k = ck % 9;
        float a, b;
        if (cp < 64)      { a = wcx0[(o * 131 + 2 * cp) * 9 + k];
                            b = wcx0[(o * 131 + 2 * cp + 1) * 9 + k]; }
        else if (cp == 64){ a = wcx0[(o * 131 + 130) * 9 + k]; b = 0.0f; }
        else              { a = wcx0[(o * 131 + 128) * 9 + k];
                            b = wcx0[(o * 131 + 129) * 9 + k]; }
        g_p_cx0[i] = make_float2(a, b);
        return;
    }
    i -= s2;
    if (i < s3) {
        int o = i % 256, ck = i / 256, cp = ck / 9, k = ck % 9;
        g_p_ch0[i] = make_float2(wch0[(o * 64 + 2 * cp) * 9 + k],
                                 wch0[(o * 64 + 2 * cp + 1) * 9 + k]);
        return;
    }
    i -= s3;
    if (i < s3) {
        int o = i % 256, ck = i / 256, cp = ck / 9, k = ck % 9;
        g_p_cx1[i] = make_float2(wcx1[(o * 64 + 2 * cp) * 9 + k],
                                 wcx1[(o * 64 + 2 * cp + 1) * 9 + k]);
        return;
    }
    i -= s3;
    if (i < s3) {
        int o = i % 256, ck = i / 256, cp = ck / 9, k = ck % 9;
        g_p_ch1[i] = make_float2(wch1[(o * 64 + 2 * cp) * 9 + k],
                                 wch1[(o * 64 + 2 * cp + 1) * 9 + k]);
        return;
    }
}

// ---------------- packed fp32x2 helpers ----------------
__device__ __forceinline__ void ffma2(unsigned long long& d, unsigned long long a,
                                      unsigned long long b)
{
    asm("fma.rn.f32x2 %0, %1, %2, %0;" : "+l"(d) : "l"(a), "l"(b));
}
__device__ __forceinline__ unsigned long long pack2(float lo, float hi)
{
    unsigned long long r;
    asm("mov.b64 %0, {%1, %2};" : "=l"(r) : "f"(lo), "f"(hi));
    return r;
}
__device__ __forceinline__ float fold2(unsigned long long v)
{
    float lo, hi;
    asm("mov.b64 {%0, %1}, %2;" : "=f"(lo), "=f"(hi) : "l"(v));
    return lo + hi;
}
// padded pair-plane pixel address (floats): rows padded to 10 u64 (20 floats)
__device__ __forceinline__ int pidx(int p)
{
    return ((p / 7 + 1) * 10 + (p % 7) + 1) * 2;
}
__device__ __forceinline__ float sigm(float v) { return 1.0f / (1.0f + expf(-v)); }

// 3x3 SAME conv over channel-pair-interleaved padded planes (u64 = float pair).
// plane: [cp][9 rows x 10 u64]; input-row-major, zero-register weight pipeline.
// Per-acc term order: (ky 0,1,2)x(kx 0,1,2) per cp — identical to prior rounds.
template <int NR, int R0, int OS>
__device__ __forceinline__ void conv_rm(const float2* __restrict__ W, const int CP,
                                        const float* __restrict__ plane,
                                        const int o, unsigned long long* acc)
{
    const unsigned long long* pb = (const unsigned long long*)plane + R0 * 10;
    const unsigned long long* wptr = (const unsigned long long*)W + o;

    unsigned long long wA[9];
#pragma unroll
    for (int k = 0; k < 9; ++k) wA[k] = __ldg(wptr + k * OS);

    for (int cp = 0; cp < CP; ++cp) {
        const unsigned long long* wnext = (cp + 1 < CP) ? wptr + 9 * OS : wptr;

#pragma unroll
        for (int ri = 0; ri < NR + 2; ++ri) {          // input row R0 + ri
            unsigned long long row[9];
            const ulonglong2* rp = (const ulonglong2*)(pb + ri * 10);
#pragma unroll
            for (int j = 0; j < 4; ++j) {
                ulonglong2 q = rp[j];
                row[2 * j] = q.x;
                row[2 * j + 1] = q.y;
            }
            row[8] = (pb + ri * 10)[8];
#pragma unroll
            for (int ky = 0; ky < 3; ++ky) {
                const int ry = ri - ky;
                if (ry >= 0 && ry < NR) {
#pragma unroll
                    for (int kx = 0; kx < 3; ++kx) {
                        const unsigned long long wv = wA[ky * 3 + kx];
#pragma unroll
                        for (int x = 0; x < 7; ++x)
                            ffma2(acc[ry * 7 + x], wv, row[x + kx]);
                    }
                }
            }
            if (ri == NR - 1) {
#pragma unroll
                for (int k = 0; k < 3; ++k) wA[k] = __ldg(wnext + k * OS);
            }
            if (ri == NR) {
#pragma unroll
                for (int k = 3; k < 6; ++k) wA[k] = __ldg(wnext + k * OS);
            }
            if (ri == NR + 1) {
#pragma unroll
                for (int k = 6; k < 9; ++k) wA[k] = __ldg(wnext + k * OS);
            }
        }
        pb += 90;
        wptr = wnext;
    }
}

// ---------------- SMEM layout (floats; planes = 180 floats/cp) ----------------
//   h0P @ 0     : 5760     h1P @ 5760 : 5760      (phase A: xinHalf 64cp = 11520)
//   gsm @ 11520 : 256*50 = 12800                  (phase A: xoutP 64cp = 11520)
//   vtxP@ 24320 : 180      vfP @ 24500 : 180      lg @ 24680 : 52
// total 24732 -> 98.9KB per CTA, 2 CTAs/SM = 198KB < 228KB
#define SM_H0   0
#define SM_H1   5760
#define SM_G    11520
#define SM_VTX  24320
#define SM_VF   24500
#define SM_LG   24680
#define SMEM_FLOATS 24736

#define NT 256

__global__ __launch_bounds__(NT, 2)
void polyrnn_main(const float* __restrict__ x, const int* __restrict__ first_vertex,
                  const float* __restrict__ b0, const float* __restrict__ b1,
                  const float* __restrict__ bcx0, const float* __restrict__ bch0,
                  const float* __restrict__ bcx1, const float* __restrict__ bch1,
                  const float* __restrict__ fcw, const float* __restrict__ fcb,
                  float* __restrict__ out)
{
    extern __shared__ float sm[];
    float* h0P   = sm + SM_H0;
    float* h1P   = sm + SM_H1;
    float* gsm   = sm + SM_G;
    float* vtxP  = sm + SM_VTX;
    float* vfP   = sm + SM_VF;
    float* lg    = sm + SM_LG;
    float* xin   = sm;            // phase A: streamed 64-cp input half / x2P
    float* xoutP = sm + SM_G;     // phase A: conv0 output (64 cp)

    const int s   = blockIdx.x;
    const int tid = threadIdx.x;

    // ---- 1: zero ALL smem (borders must be 0) ----
    for (int i = tid; i < SMEM_FLOATS; i += NT) sm[i] = 0.0f;
    __syncthreads();

    const float* xs = x + (size_t)s * (256 * 49);
    const int o7 = tid & 127, q = tid >> 7;   // q=0: rows 0-3 (28 acc), q=1: rows 4-6 (21)

    // ---- 2+3: conv0 (256->128) + ReLU, streamed over two 64-cp input halves ----
    {
        const unsigned long long binit = pack2(b0[o7], 0.0f);
        unsigned long long a0[28];
#pragma unroll
        for (int i = 0; i < 28; ++i) a0[i] = binit;

        // half 1: channels 0..127 -> cps 0..63
        for (int i = tid; i < 128 * 49; i += NT) {
            int c = i / 49, p = i % 49;
            xin[(c >> 1) * 180 + pidx(p) + (c & 1)] = xs[i];
        }
        __syncthreads();
        if (q == 0) conv_rm<4, 0, 128>(g_p_conv0, 64, xin, o7, a0);
        else        conv_rm<3, 4, 128>(g_p_conv0, 64, xin, o7, a0);
        __syncthreads();

        // half 2: channels 128..255 -> cps 64..127
        for (int i = tid; i < 128 * 49; i += NT) {
            int c = i / 49, p = i % 49;
            xin[(c >> 1) * 180 + pidx(p) + (c & 1)] = xs[128 * 49 + i];
        }
        __syncthreads();
        if (q == 0) conv_rm<4, 0, 128>(g_p_conv0 + 64 * 9 * 128, 64, xin, o7, a0);
        else        conv_rm<3, 4, 128>(g_p_conv0 + 64 * 9 * 128, 64, xin, o7, a0);

        const int nr = q ? 3 : 4, r0 = q ? 4 : 0;
        for (int lr = 0; lr < nr; ++lr)
#pragma unroll
            for (int xq = 0; xq < 7; ++xq)
                xoutP[(o7 >> 1) * 180 + pidx((r0 + lr) * 7 + xq) + (o7 & 1)] =
                    fmaxf(fold2(a0[lr * 7 + xq]), 0.0f);
    }
    __syncthreads();

    // ---- 4: conv1 (128->128) + ReLU -> x2P (xin region; same geometry, borders 0) ----
    {
        const unsigned long long binit = pack2(b1[o7], 0.0f);
        unsigned long long a1[28];
#pragma unroll
        for (int i = 0; i < 28; ++i) a1[i] = binit;
        if (q == 0) conv_rm<4, 0, 128>(g_p_conv1, 64, xoutP, o7, a1);
        else        conv_rm<3, 4, 128>(g_p_conv1, 64, xoutP, o7, a1);
        __syncthreads();   // all reads of xoutP done before any thread could race (regions distinct anyway)
        const int nr = q ? 3 : 4, r0 = q ? 4 : 0;
        for (int lr = 0; lr < nr; ++lr)
#pragma unroll
            for (int xq = 0; xq < 7; ++xq)
                xin[(o7 >> 1) * 180 + pidx((r0 + lr) * 7 + xq) + (o7 & 1)] =
                    fmaxf(fold2(a1[lr * 7 + xq]), 0.0f);
    }
    // ---- 5: v_first plane (vfP zeroed at start) ----
    if (tid == 0) {
        int v = first_vertex[s];             // [0,48]
        vfP[pidx(v) + 0] = 1.0f;             // (v_first, 0) pair
    }
    __syncthreads();

    // ---- 6: const gates: g_gxc = bias_g0 + conv(x2P cps0..63 + vfP; cx0), transposed ----
    {
        const float bg0 = bcx0[tid] + bch0[tid];
        float* gx = g_gxc + (size_t)s * 12544;
        {
            unsigned long long a[28];
            const unsigned long long binit = pack2(bg0, 0.0f);
#pragma unroll
            for (int i = 0; i < 28; ++i) a[i] = binit;
            conv_rm<4, 0, 256>(g_p_cx0, 64, xin, tid, a);
            conv_rm<4, 0, 256>(g_p_cx0 + 64 * 9 * 256, 1, vfP, tid, a);
#pragma unroll
            for (int i = 0; i < 28; ++i) gx[i * 256 + tid] = fold2(a[i]);
        }
        {
            unsigned long long a[21];
#pragma unroll
            for (int i = 0; i < 21; ++i) a[i] = pack2(0.0f, 0.0f);
            conv_rm<3, 4, 256>(g_p_cx0, 64, xin, tid, a);
            conv_rm<3, 4, 256>(g_p_cx0 + 64 * 9 * 256, 1, vfP, tid, a);
#pragma unroll
            for (int i = 0; i < 21; ++i) gx[(28 + i) * 256 + tid] = bg0 + fold2(a[i]);
        }
    }
    __syncthreads();

    // ---- 7: zero h planes (x2P junk) + c state; init v_p1 = v_first one-hot ----
    for (int i = tid; i < 11520; i += NT) sm[i] = 0.0f;
    if (tid < 180) vtxP[tid] = 0.0f;
    {
        float* cg = g_c + (size_t)s * 6272;
        for (int i = tid; i < 6272; i += NT) cg[i] = 0.0f;
    }
    __syncthreads();
    if (tid == 0) {
        int v = first_vertex[s];
        vtxP[pidx(v) + 1] = 1.0f;            // (v_p2, v_p1): hi lane = v_p1
    }
    __syncthreads();

    const float bias_g1 = bcx1[tid] + bch1[tid];
    const float2* cx0_dyn = g_p_cx0 + 65 * 9 * 256;   // dynamic (v_p2, v_p1) pair weights
    const float* gx = g_gxc + (size_t)s * 12544;
    float* cg0 = g_c + (size_t)s * 6272;
    float* cg1 = cg0 + 3136;
    const int warp = tid >> 5, lane = tid & 31;

    for (int t = 0; t < STEPS; ++t) {
        // ---- layer0 gates: gxc + conv(vtxP; cx0_dyn) + conv(h0P; ch0); two row passes ----
        {
            unsigned long long a[28];
#pragma unroll
            for (int i = 0; i < 28; ++i) a[i] = pack2(gx[i * 256 + tid], 0.0f);
            conv_rm<4, 0, 256>(cx0_dyn, 1, vtxP, tid, a);
            conv_rm<4, 0, 256>(g_p_ch0, 32, h0P, tid, a);
#pragma unroll
            for (int i = 0; i < 14; ++i) {
                unsigned long long pv = pack2(fold2(a[2 * i]), fold2(a[2 * i + 1]));
                *(unsigned long long*)(gsm + tid * 50 + 2 * i) = pv;
            }
        }
        {
            unsigned long long a[21];
#pragma unroll
            for (int i = 0; i < 21; ++i) a[i] = pack2(gx[(28 + i) * 256 + tid], 0.0f);
            conv_rm<3, 4, 256>(cx0_dyn, 1, vtxP, tid, a);
            conv_rm<3, 4, 256>(g_p_ch0, 32, h0P, tid, a);
#pragma unroll
            for (int i = 0; i < 10; ++i) {
                unsigned long long pv = pack2(fold2(a[2 * i]), fold2(a[2 * i + 1]));
                *(unsigned long long*)(gsm + tid * 50 + 28 + 2 * i) = pv;
            }
            gsm[tid * 50 + 48] = fold2(a[20]);
        }
        __syncthreads();

        // ---- LSTM0 (c in global, same-thread mapping) ----
        for (int i = tid; i < 3136; i += NT) {
            int c = i / 49, p = i - c * 49;
            float ig = sigm(gsm[c * 50 + p]);
            float fg = sigm(gsm[(c + 64) * 50 + p]);
            float gg = tanhf(gsm[(c + 128) * 50 + p]);
            float og = sigm(gsm[(c + 192) * 50 + p]);
            float cy = fg * cg0[i] + ig * gg;
            cg0[i] = cy;
            h0P[(c >> 1) * 180 + pidx(p) + (c & 1)] = og * tanhf(cy);
        }
        __syncthreads();

        // ---- layer1 gates: conv(h0P; cx1) + conv(h1P; ch1); two row passes ----
        {
            unsigned long long a[28];
            const unsigned long long binit = pack2(bias_g1, 0.0f);
#pragma unroll
            for (int i = 0; i < 28; ++i) a[i] = binit;
            conv_rm<4, 0, 256>(g_p_cx1, 32, h0P, tid, a);
            conv_rm<4, 0, 256>(g_p_ch1, 32, h1P, tid, a);
#pragma unroll
            for (int i = 0; i < 14; ++i) {
                unsigned long long pv = pack2(fold2(a[2 * i]), fold2(a[2 * i + 1]));
                *(unsigned long long*)(gsm + tid * 50 + 2 * i) = pv;
            }
        }
        {
            unsigned long long a[21];
            const unsigned long long binit = pack2(bias_g1, 0.0f);
#pragma unroll
            for (int i = 0; i < 21; ++i) a[i] = binit;
            conv_rm<3, 4, 256>(g_p_cx1, 32, h0P, tid, a);
            conv_rm<3, 4, 256>(g_p_ch1, 32, h1P, tid, a);
#pragma unroll
            for (int i = 0; i < 10; ++i) {
                unsigned long long pv = pack2(fold2(a[2 * i]), fold2(a[2 * i + 1]));
                *(unsigned long long*)(gsm + tid * 50 + 28 + 2 * i) = pv;
            }
            gsm[tid * 50 + 48] = fold2(a[20]);
        }
        __syncthreads();

        // ---- LSTM1 ----
        for (int i = tid; i < 3136; i += NT) {
            int c = i / 49, p = i - c * 49;
            float ig = sigm(gsm[c * 50 + p]);
            float fg = sigm(gsm[(c + 64) * 50 + p]);
            float gg = tanhf(gsm[(c + 128) * 50 + p]);
            float og = sigm(gsm[(c + 192) * 50 + p]);
            float cy = fg * cg1[i] + ig * gg;
            cg1[i] = cy;
            h1P[(c >> 1) * 180 + pidx(p) + (c & 1)] = og * tanhf(cy);
        }
        __syncthreads();

        // ---- fc: logits[50] over 8 warps ----
        for (int o = warp; o < 50; o += 8) {
            float ssum = 0.0f;
            const float* wr = fcw + o * 3136;
            int c = 0, p = lane;
            for (int j = lane; j < 3136; j += 32) {
                ssum += wr[j] * h1P[(c >> 1) * 180 + pidx(p) + (c & 1)];
                p += 32;
                if (p >= 49) { p -= 49; ++c; }
            }
#pragma unroll
            for (int d = 16; d; d >>= 1) ssum += __shfl_down_sync(0xffffffffu, ssum, d);
            if (lane == 0) lg[o] = ssum + fcb[o];
        }
        __syncthreads();

        // ---- emit; fused argmax + feedback in warp 0 (first-max-wins) ----
        if (tid < 50) out[((size_t)s * STEPS + t) * 50 + tid] = lg[tid];
        if (warp == 0) {
            float bv = lg[lane];
            int bi = lane;
            float v2 = (lane < 18) ? lg[32 + lane] : -3.402823466e38f;
            if (v2 > bv) { bv = v2; bi = 32 + lane; }
#pragma unroll
            for (int d = 16; d; d >>= 1) {
                float ov = __shfl_down_sync(0xffffffffu, bv, d);
                int   oi = __shfl_down_sync(0xffffffffu, bi, d);
                if (ov > bv || (ov == bv && oi < bi)) { bv = ov; bi = oi; }
            }
            bi = __shfl_sync(0xffffffffu, bi, 0);
            for (int p4 = lane; p4 < 49; p4 += 32) {
                int a2 = pidx(p4);
                vtxP[a2 + 0] = vtxP[a2 + 1];
                vtxP[a2 + 1] = (bi == p4) ? 1.0f : 0.0f;
            }
        }
        __syncthreads();
    }
}

extern "C" void kernel_launch(void* const* d_in, const int* in_sizes, int n_in,
                              void* d_out, int out_size)
{
    const float* x    = (const float*)d_in[0];
    const int*   fv   = (const int*)  d_in[1];
    const float* w0   = (const float*)d_in[2];
    const float* b0   = (const float*)d_in[3];
    const float* w1   = (const float*)d_in[4];
    const float* b1   = (const float*)d_in[5];
    const float* wcx0 = (const float*)d_in[6];
    const float* bcx0 = (const float*)d_in[7];
    const float* wch0 = (const float*)d_in[8];
    const float* bch0 = (const float*)d_in[9];
    const float* wcx1 = (const float*)d_in[10];
    const float* bcx1 = (const float*)d_in[11];
    const float* wch1 = (const float*)d_in[12];
    const float* bch1 = (const float*)d_in[13];
    const float* fcw  = (const float*)d_in[14];
    const float* fcb  = (const float*)d_in[15];
    float* out = (float*)d_out;

    const int n = in_sizes[1];  // batch (2048)

    const int total = 128 * 9 * 128 + 64 * 9 * 128 + 66 * 9 * 256 + 3 * 32 * 9 * 256;
    pack_weights<<<(total + 255) / 256, 256>>>(w0, w1, wcx0, wch0, wcx1, wch1);

    const int smem_bytes = SMEM_FLOATS * 4;
    cudaFuncSetAttribute(polyrnn_main, cudaFuncAttributeMaxDynamicSharedMemorySize, smem_bytes);
    polyrnn_main<<<n, NT, smem_bytes>>>(x, fv, b0, b1, bcx0, bch0, bcx1, bch1, fcw, fcb, out);
}

// round 12
// speedup vs baseline: 2.1199x; 1.1169x over previous
#include <cuda_runtime.h>
#include <math.h>

#define STEPS 9
#define NBATCH 2048

// ---------------- packed pair weights (device globals; no allocation) ----
// layout: [(cpair*9 + k) * O + o] as float2
__device__ float2 g_p_conv0[128 * 9 * 128];  // C=256 -> 128 cp, O=128
__device__ float2 g_p_conv1[ 64 * 9 * 128];  // C=128 -> 64 cp,  O=128
// cx0 cp order: cp0..63 = x channel pairs; cp64 = (ch130 v_first, 0); cp65 = (v_p2, v_p1)
__device__ float2 g_p_cx0 [ 66 * 9 * 256];
__device__ float2 g_p_ch0 [ 32 * 9 * 256];
__device__ float2 g_p_cx1 [ 32 * 9 * 256];
__device__ float2 g_p_ch1 [ 32 * 9 * 256];
__device__ float2 g_p_fc  [ 50 * 1568];          // fc pair-packed: [o][cp*49+p]
// per-sample scratch (moved out of smem to allow 2 CTAs/SM)
__device__ float g_gxc[(size_t)NBATCH * 12544];  // const gates, TRANSPOSED [i*256+o]
__device__ float g_c  [(size_t)NBATCH * 6272];   // c0 (3136) + c1 (3136)

__global__ void pack_weights(const float* __restrict__ w0, const float* __restrict__ w1,
                             const float* __restrict__ wcx0, const float* __restrict__ wch0,
                             const float* __restrict__ wcx1, const float* __restrict__ wch1,
                             const float* __restrict__ fcw)
{
    int i = blockIdx.x * blockDim.x + threadIdx.x;
    const int s0 = 128 * 9 * 128, s1 = 64 * 9 * 128, s2 = 66 * 9 * 256, s3 = 32 * 9 * 256;
    if (i < s0) {
        int o = i % 128, ck = i / 128, cp = ck / 9, k = ck % 9;
        g_p_conv0[i] = make_float2(w0[(o * 256 + 2 * cp) * 9 + k],
                                   w0[(o * 256 + 2 * cp + 1) * 9 + k]);
        return;
    }
    i -= s0;
    if (i < s1) {
        int o = i % 128, ck = i / 128, cp = ck / 9, k = ck % 9;
        g_p_conv1[i] = make_float2(w1[(o * 128 + 2 * cp) * 9 + k],
                                   w1[(o * 128 + 2 * cp + 1) * 9 + k]);
        return;
    }
    i -= s1;
    if (i < s2) {
        int o = i % 256, ck = i / 256, cp = ck / 9, k = ck % 9;
        float a, b;
        if (cp < 64)      { a = wcx0[(o * 131 + 2 * cp) * 9 + k];
                            b = wcx0[(o * 131 + 2 * cp + 1) * 9 + k]; }
        else if (cp == 64){ a = wcx0[(o * 131 + 130) * 9 + k]; b = 0.0f; }
        else              { a = wcx0[(o * 131 + 128) * 9 + k];
                            b = wcx0[(o * 131 + 129) * 9 + k]; }
        g_p_cx0[i] = make_float2(a, b);
        return;
    }
    i -= s2;
    if (i < s3) {
        int o = i % 256, ck = i / 256, cp = ck / 9, k = ck % 9;
        g_p_ch0[i] = make_float2(wch0[(o * 64 + 2 * cp) * 9 + k],
                                 wch0[(o * 64 + 2 * cp + 1) * 9 + k]);
        return;
    }
    i -= s3;
    if (i < s3) {
        int o = i % 256, ck = i / 256, cp = ck / 9, k = ck % 9;
        g_p_cx1[i] = make_float2(wcx1[(o * 64 + 2 * cp) * 9 + k],
                                 wcx1[(o * 64 + 2 * cp + 1) * 9 + k]);
        return;
    }
    i -= s3;
    if (i < s3) {
        int o = i % 256, ck = i / 256, cp = ck / 9, k = ck % 9;
        g_p_ch1[i] = make_float2(wch1[(o * 64 + 2 * cp) * 9 + k],
                                 wch1[(o * 64 + 2 * cp + 1) * 9 + k]);
        return;
    }
    i -= s3;
    if (i < 50 * 1568) {
        int o = i / 1568, e = i % 1568, cp = e / 49, p = e % 49;
        g_p_fc[i] = make_float2(fcw[o * 3136 + (2 * cp) * 49 + p],
                                fcw[o * 3136 + (2 * cp + 1) * 49 + p]);
        return;
    }
}

// ---------------- packed fp32x2 helpers ----------------
__device__ __forceinline__ void ffma2(unsigned long long& d, unsigned long long a,
                                      unsigned long long b)
{
    asm("fma.rn.f32x2 %0, %1, %2, %0;" : "+l"(d) : "l"(a), "l"(b));
}
__device__ __forceinline__ unsigned long long pack2(float lo, float hi)
{
    unsigned long long r;
    asm("mov.b64 %0, {%1, %2};" : "=l"(r) : "f"(lo), "f"(hi));
    return r;
}
__device__ __forceinline__ float fold2(unsigned long long v)
{
    float lo, hi;
    asm("mov.b64 {%0, %1}, %2;" : "=f"(lo), "=f"(hi) : "l"(v));
    return lo + hi;
}
// padded pair-plane pixel address (floats): rows padded to 10 u64 (20 floats)
__device__ __forceinline__ int pidx(int p)
{
    return ((p / 7 + 1) * 10 + (p % 7) + 1) * 2;
}
__device__ __forceinline__ int pidx64(int p)   // u64-granular index
{
    return (p / 7 + 1) * 10 + (p % 7) + 1;
}
__device__ __forceinline__ float sigm(float v) { return 1.0f / (1.0f + expf(-v)); }

// 3x3 SAME conv over channel-pair-interleaved padded planes (u64 = float pair).
// plane: [cp][9 rows x 10 u64]; input-row-major, zero-register weight pipeline.
// Per-acc term order: (ky 0,1,2)x(kx 0,1,2) per cp — identical to prior rounds.
template <int NR, int R0, int OS>
__device__ __forceinline__ void conv_rm(const float2* __restrict__ W, const int CP,
                                        const float* __restrict__ plane,
                                        const int o, unsigned long long* acc)
{
    const unsigned long long* pb = (const unsigned long long*)plane + R0 * 10;
    const unsigned long long* wptr = (const unsigned long long*)W + o;

    unsigned long long wA[9];
#pragma unroll
    for (int k = 0; k < 9; ++k) wA[k] = __ldg(wptr + k * OS);

    for (int cp = 0; cp < CP; ++cp) {
        const unsigned long long* wnext = (cp + 1 < CP) ? wptr + 9 * OS : wptr;

#pragma unroll
        for (int ri = 0; ri < NR + 2; ++ri) {          // input row R0 + ri
            unsigned long long row[9];
            const ulonglong2* rp = (const ulonglong2*)(pb + ri * 10);
#pragma unroll
            for (int j = 0; j < 4; ++j) {
                ulonglong2 q = rp[j];
                row[2 * j] = q.x;
                row[2 * j + 1] = q.y;
            }
            row[8] = (pb + ri * 10)[8];
#pragma unroll
            for (int ky = 0; ky < 3; ++ky) {
                const int ry = ri - ky;
                if (ry >= 0 && ry < NR) {
#pragma unroll
                    for (int kx = 0; kx < 3; ++kx) {
                        const unsigned long long wv = wA[ky * 3 + kx];
#pragma unroll
                        for (int x = 0; x < 7; ++x)
                            ffma2(acc[ry * 7 + x], wv, row[x + kx]);
                    }
                }
            }
            if (ri == NR - 1) {
#pragma unroll
                for (int k = 0; k < 3; ++k) wA[k] = __ldg(wnext + k * OS);
            }
            if (ri == NR) {
#pragma unroll
                for (int k = 3; k < 6; ++k) wA[k] = __ldg(wnext + k * OS);
            }
            if (ri == NR + 1) {
#pragma unroll
                for (int k = 6; k < 9; ++k) wA[k] = __ldg(wnext + k * OS);
            }
        }
        pb += 90;
        wptr = wnext;
    }
}

// ---------------- SMEM layout (floats; planes = 180 floats/cp) ----------------
//   h0P @ 0     : 5760     h1P @ 5760 : 5760      (phase A: xinHalf 64cp = 11520)
//   gsm @ 11520 : 256*50 = 12800                  (phase A: xoutP 64cp = 11520)
//   vtxP@ 24320 : 180      vfP @ 24500 : 180      lg @ 24680 : 52
#define SM_H0   0
#define SM_H1   5760
#define SM_G    11520
#define SM_VTX  24320
#define SM_VF   24500
#define SM_LG   24680
#define SMEM_FLOATS 24736

#define NT 256

__global__ __launch_bounds__(NT, 2)
void polyrnn_main(const float* __restrict__ x, const int* __restrict__ first_vertex,
                  const float* __restrict__ b0, const float* __restrict__ b1,
                  const float* __restrict__ bcx0, const float* __restrict__ bch0,
                  const float* __restrict__ bcx1, const float* __restrict__ bch1,
                  const float* __restrict__ fcw, const float* __restrict__ fcb,
                  float* __restrict__ out)
{
    extern __shared__ float sm[];
    float* h0P   = sm + SM_H0;
    float* h1P   = sm + SM_H1;
    float* gsm   = sm + SM_G;
    float* vtxP  = sm + SM_VTX;
    float* vfP   = sm + SM_VF;
    float* lg    = sm + SM_LG;
    float* xin   = sm;            // phase A: streamed 64-cp input half / x2P
    float* xoutP = sm + SM_G;     // phase A: conv0 output (64 cp)

    const int s   = blockIdx.x;
    const int tid = threadIdx.x;

    // ---- 1: zero ALL smem (borders must be 0) ----
    for (int i = tid; i < SMEM_FLOATS; i += NT) sm[i] = 0.0f;
    __syncthreads();

    const float* xs = x + (size_t)s * (256 * 49);
    const int o7 = tid & 127, q = tid >> 7;   // q=0: rows 0-3 (28 acc), q=1: rows 4-6 (21)

    // ---- 2+3: conv0 (256->128) + ReLU, streamed over two 64-cp input halves ----
    {
        const unsigned long long binit = pack2(b0[o7], 0.0f);
        unsigned long long a0[28];
#pragma unroll
        for (int i = 0; i < 28; ++i) a0[i] = binit;

        for (int i = tid; i < 128 * 49; i += NT) {
            int c = i / 49, p = i % 49;
            xin[(c >> 1) * 180 + pidx(p) + (c & 1)] = xs[i];
        }
        __syncthreads();
        if (q == 0) conv_rm<4, 0, 128>(g_p_conv0, 64, xin, o7, a0);
        else        conv_rm<3, 4, 128>(g_p_conv0, 64, xin, o7, a0);
        __syncthreads();

        for (int i = tid; i < 128 * 49; i += NT) {
            int c = i / 49, p = i % 49;
            xin[(c >> 1) * 180 + pidx(p) + (c & 1)] = xs[128 * 49 + i];
        }
        __syncthreads();
        if (q == 0) conv_rm<4, 0, 128>(g_p_conv0 + 64 * 9 * 128, 64, xin, o7, a0);
        else        conv_rm<3, 4, 128>(g_p_conv0 + 64 * 9 * 128, 64, xin, o7, a0);

        const int nr = q ? 3 : 4, r0 = q ? 4 : 0;
        for (int lr = 0; lr < nr; ++lr)
#pragma unroll
            for (int xq = 0; xq < 7; ++xq)
                xoutP[(o7 >> 1) * 180 + pidx((r0 + lr) * 7 + xq) + (o7 & 1)] =
                    fmaxf(fold2(a0[lr * 7 + xq]), 0.0f);
    }
    __syncthreads();

    // ---- 4: conv1 (128->128) + ReLU -> x2P (xin region) ----
    {
        const unsigned long long binit = pack2(b1[o7], 0.0f);
        unsigned long long a1[28];
#pragma unroll
        for (int i = 0; i < 28; ++i) a1[i] = binit;
        if (q == 0) conv_rm<4, 0, 128>(g_p_conv1, 64, xoutP, o7, a1);
        else        conv_rm<3, 4, 128>(g_p_conv1, 64, xoutP, o7, a1);
        __syncthreads();
        const int nr = q ? 3 : 4, r0 = q ? 4 : 0;
        for (int lr = 0; lr < nr; ++lr)
#pragma unroll
            for (int xq = 0; xq < 7; ++xq)
                xin[(o7 >> 1) * 180 + pidx((r0 + lr) * 7 + xq) + (o7 & 1)] =
                    fmaxf(fold2(a1[lr * 7 + xq]), 0.0f);
    }
    // ---- 5: v_first plane (vfP zeroed at start) ----
    if (tid == 0) {
        int v = first_vertex[s];             // [0,48]
        vfP[pidx(v) + 0] = 1.0f;             // (v_first, 0) pair
    }
    __syncthreads();

    // ---- 6: const gates: g_gxc = bias_g0 + conv(x2P cps0..63 + vfP; cx0), transposed ----
    {
        const float bg0 = bcx0[tid] + bch0[tid];
        float* gx = g_gxc + (size_t)s * 12544;
        {
            unsigned long long a[28];
            const unsigned long long binit = pack2(bg0, 0.0f);
#pragma unroll
            for (int i = 0; i < 28; ++i) a[i] = binit;
            conv_rm<4, 0, 256>(g_p_cx0, 64, xin, tid, a);
            conv_rm<4, 0, 256>(g_p_cx0 + 64 * 9 * 256, 1, vfP, tid, a);
#pragma unroll
            for (int i = 0; i < 28; ++i) gx[i * 256 + tid] = fold2(a[i]);
        }
        {
            unsigned long long a[21];
#pragma unroll
            for (int i = 0; i < 21; ++i) a[i] = pack2(0.0f, 0.0f);
            conv_rm<3, 4, 256>(g_p_cx0, 64, xin, tid, a);
            conv_rm<3, 4, 256>(g_p_cx0 + 64 * 9 * 256, 1, vfP, tid, a);
#pragma unroll
            for (int i = 0; i < 21; ++i) gx[(28 + i) * 256 + tid] = bg0 + fold2(a[i]);
        }
    }
    __syncthreads();

    // ---- 7: zero h planes (x2P junk); init v_p1 = v_first one-hot ----
    for (int i = tid; i < 11520; i += NT) sm[i] = 0.0f;
    if (tid < 180) vtxP[tid] = 0.0f;
    __syncthreads();
    if (tid == 0) {
        int v = first_vertex[s];
        vtxP[pidx(v) + 1] = 1.0f;            // (v_p2, v_p1): hi lane = v_p1
    }
    __syncthreads();

    const float bias_g1 = bcx1[tid] + bch1[tid];
    const float2* cx0_dyn = g_p_cx0 + 65 * 9 * 256;   // dynamic (v_p2, v_p1) pair weights
    const float* gx = g_gxc + (size_t)s * 12544;
    float* cg0 = g_c + (size_t)s * 6272;
    float* cg1 = cg0 + 3136;
    const int warp = tid >> 5, lane = tid & 31;

    for (int t = 0; t < STEPS; ++t) {
        // ---- layer0 gates: gxc + conv(vtxP; cx0_dyn) + conv(h0P; ch0) ----
        // t=0: h0P == 0 -> skipping ch0 conv is bit-identical (fma(w,0,a)==a)
        {
            unsigned long long a[28];
#pragma unroll
            for (int i = 0; i < 28; ++i) a[i] = pack2(gx[i * 256 + tid], 0.0f);
            conv_rm<4, 0, 256>(cx0_dyn, 1, vtxP, tid, a);
            if (t > 0) conv_rm<4, 0, 256>(g_p_ch0, 32, h0P, tid, a);
#pragma unroll
            for (int i = 0; i < 14; ++i) {
                unsigned long long pv = pack2(fold2(a[2 * i]), fold2(a[2 * i + 1]));
                *(unsigned long long*)(gsm + tid * 50 + 2 * i) = pv;
            }
        }
        {
            unsigned long long a[21];
#pragma unroll
            for (int i = 0; i < 21; ++i) a[i] = pack2(gx[(28 + i) * 256 + tid], 0.0f);
            conv_rm<3, 4, 256>(cx0_dyn, 1, vtxP, tid, a);
            if (t > 0) conv_rm<3, 4, 256>(g_p_ch0, 32, h0P, tid, a);
#pragma unroll
            for (int i = 0; i < 10; ++i) {
                unsigned long long pv = pack2(fold2(a[2 * i]), fold2(a[2 * i + 1]));
                *(unsigned long long*)(gsm + tid * 50 + 28 + 2 * i) = pv;
            }
            gsm[tid * 50 + 48] = fold2(a[20]);
        }
        __syncthreads();

        // ---- LSTM0 (c in global; t=0 treats c_prev = 0, no zero-pass needed) ----
        for (int i = tid; i < 3136; i += NT) {
            int c = i / 49, p = i - c * 49;
            float ig = sigm(gsm[c * 50 + p]);
            float fg = sigm(gsm[(c + 64) * 50 + p]);
            float gg = tanhf(gsm[(c + 128) * 50 + p]);
            float og = sigm(gsm[(c + 192) * 50 + p]);
            float cprev = (t == 0) ? 0.0f : cg0[i];
            float cy = fg * cprev + ig * gg;
            cg0[i] = cy;
            h0P[(c >> 1) * 180 + pidx(p) + (c & 1)] = og * tanhf(cy);
        }
        __syncthreads();

        // ---- layer1 gates: conv(h0P; cx1) + conv(h1P; ch1) ----
        // t=0: h1P == 0 -> skipping ch1 conv is bit-identical
        {
            unsigned long long a[28];
            const unsigned long long binit = pack2(bias_g1, 0.0f);
#pragma unroll
            for (int i = 0; i < 28; ++i) a[i] = binit;
            conv_rm<4, 0, 256>(g_p_cx1, 32, h0P, tid, a);
            if (t > 0) conv_rm<4, 0, 256>(g_p_ch1, 32, h1P, tid, a);
#pragma unroll
            for (int i = 0; i < 14; ++i) {
                unsigned long long pv = pack2(fold2(a[2 * i]), fold2(a[2 * i + 1]));
                *(unsigned long long*)(gsm + tid * 50 + 2 * i) = pv;
            }
        }
        {
            unsigned long long a[21];
            const unsigned long long binit = pack2(bias_g1, 0.0f);
#pragma unroll
            for (int i = 0; i < 21; ++i) a[i] = binit;
            conv_rm<3, 4, 256>(g_p_cx1, 32, h0P, tid, a);
            if (t > 0) conv_rm<3, 4, 256>(g_p_ch1, 32, h1P, tid, a);
#pragma unroll
            for (int i = 0; i < 10; ++i) {
                unsigned long long pv = pack2(fold2(a[2 * i]), fold2(a[2 * i + 1]));
                *(unsigned long long*)(gsm + tid * 50 + 28 + 2 * i) = pv;
            }
            gsm[tid * 50 + 48] = fold2(a[20]);
        }
        __syncthreads();

        // ---- LSTM1 ----
        for (int i = tid; i < 3136; i += NT) {
            int c = i / 49, p = i - c * 49;
            float ig = sigm(gsm[c * 50 + p]);
            float fg = sigm(gsm[(c + 64) * 50 + p]);
            float gg = tanhf(gsm[(c + 128) * 50 + p]);
            float og = sigm(gsm[(c + 192) * 50 + p]);
            float cprev = (t == 0) ? 0.0f : cg1[i];
            float cy = fg * cprev + ig * gg;
            cg1[i] = cy;
            h1P[(c >> 1) * 180 + pidx(p) + (c & 1)] = og * tanhf(cy);
        }
        __syncthreads();

        // ---- fc: logits[50] over 8 warps, pair-packed FFMA2 ----
        for (int o = warp; o < 50; o += 8) {
            unsigned long long asum = pack2(0.0f, 0.0f);
            const unsigned long long* wr = (const unsigned long long*)g_p_fc + o * 1568;
            const unsigned long long* h1u = (const unsigned long long*)h1P;
            int cp = 0, p = lane;
            for (int e = lane; e < 1568; e += 32) {
                ffma2(asum, __ldg(wr + e), h1u[cp * 90 + pidx64(p)]);
                p += 32;
                if (p >= 49) { p -= 49; ++cp; }
            }
            float ssum = fold2(asum);
#pragma unroll
            for (int d = 16; d; d >>= 1) ssum += __shfl_down_sync(0xffffffffu, ssum, d);
            if (lane == 0) lg[o] = ssum + fcb[o];
        }
        __syncthreads();

        // ---- emit; fused argmax + feedback in warp 0 (first-max-wins) ----
        if (tid < 50) out[((size_t)s * STEPS + t) * 50 + tid] = lg[tid];
        if (warp == 0) {
            float bv = lg[lane];
            int bi = lane;
            float v2 = (lane < 18) ? lg[32 + lane] : -3.402823466e38f;
            if (v2 > bv) { bv = v2; bi = 32 + lane; }
#pragma unroll
            for (int d = 16; d; d >>= 1) {
                float ov = __shfl_down_sync(0xffffffffu, bv, d);
                int   oi = __shfl_down_sync(0xffffffffu, bi, d);
                if (ov > bv || (ov == bv && oi < bi)) { bv = ov; bi = oi; }
            }
            bi = __shfl_sync(0xffffffffu, bi, 0);
            for (int p4 = lane; p4 < 49; p4 += 32) {
                int a2 = pidx(p4);
                vtxP[a2 + 0] = vtxP[a2 + 1];
                vtxP[a2 + 1] = (bi == p4) ? 1.0f : 0.0f;
            }
        }
        __syncthreads();
    }
}

extern "C" void kernel_launch(void* const* d_in, const int* in_sizes, int n_in,
                              void* d_out, int out_size)
{
    const float* x    = (const float*)d_in[0];
    const int*   fv   = (const int*)  d_in[1];
    const float* w0   = (const float*)d_in[2];
    const float* b0   = (const float*)d_in[3];
    const float* w1   = (const float*)d_in[4];
    const float* b1   = (const float*)d_in[5];
    const float* wcx0 = (const float*)d_in[6];
    const float* bcx0 = (const float*)d_in[7];
    const float* wch0 = (const float*)d_in[8];
    const float* bch0 = (const float*)d_in[9];
    const float* wcx1 = (const float*)d_in[10];
    const float* bcx1 = (const float*)d_in[11];
    const float* wch1 = (const float*)d_in[12];
    const float* bch1 = (const float*)d_in[13];
    const float* fcw  = (const float*)d_in[14];
    const float* fcb  = (const float*)d_in[15];
    float* out = (float*)d_out;

    const int n = in_sizes[1];  // batch (2048)

    const int total = 128 * 9 * 128 + 64 * 9 * 128 + 66 * 9 * 256 + 3 * 32 * 9 * 256
                    + 50 * 1568;
    pack_weights<<<(total + 255) / 256, 256>>>(w0, w1, wcx0, wch0, wcx1, wch1, fcw);

    const int smem_bytes = SMEM_FLOATS * 4;
    cudaFuncSetAttribute(polyrnn_main, cudaFuncAttributeMaxDynamicSharedMemorySize, smem_bytes);
    polyrnn_main<<<n, NT, smem_bytes>>>(x, fv, b0, b1, bcx0, bch0, bcx1, bch1, fcw, fcb, out);
}